// round 2
// baseline (speedup 1.0000x reference)
#include <cuda_runtime.h>
#include <math.h>

#define NN 100000
#define EE 1600000
#define GG 64
#define SCAN_BLK 1024
#define NBLK_SCAN ((NN + SCAN_BLK - 1) / SCAN_BLK)   // 98

// ---------------- scratch (device globals; no allocation) ----------------
__device__ __align__(16) float g_h1[(size_t)NN * 256];   // x @ W1
__device__ __align__(16) float g_e1[(size_t)NN * 256];   // elu(aggregate1)
__device__ __align__(16) float g_h2[(size_t)NN * 64];    // e1 @ W2
__device__ __align__(16) float g_o2[(size_t)NN * 64];    // aggregate2
__device__ __align__(16) float g_asrc1[NN * 4];
__device__ __align__(16) float g_adst1[NN * 4];
__device__ float g_asrc2[NN];
__device__ float g_adst2[NN];
__device__ int   g_cnt[NN];
__device__ int   g_rowptr[NN + 1];
__device__ int   g_wpos[NN];
__device__ int   g_csr[EE + NN];
__device__ int   g_part[NBLK_SCAN + 8];
__device__ float g_emb[GG * 64];

// ---------------- helpers ----------------
__device__ __forceinline__ float warpMax(float v) {
    #pragma unroll
    for (int o = 16; o; o >>= 1) v = fmaxf(v, __shfl_xor_sync(0xffffffffu, v, o));
    return v;
}
__device__ __forceinline__ float warpSum(float v) {
    #pragma unroll
    for (int o = 16; o; o >>= 1) v += __shfl_xor_sync(0xffffffffu, v, o);
    return v;
}
__device__ __forceinline__ float lrelu(float a) { return a > 0.f ? a : 0.2f * a; }

// ---------------- SGEMM: C[M,Ncol] = A[M,K] @ B[K,Ncol] ----------------
template <int BM, int BN, int BK, int TM, int TN>
__global__ __launch_bounds__((BM / TM) * (BN / TN))
void sgemm(const float* __restrict__ A, const float* __restrict__ B,
           float* __restrict__ C, int M, int K, int Ncol) {
    __shared__ __align__(16) float As[BK][BM];
    __shared__ __align__(16) float Bs[BK][BN];
    const int nth = (BM / TM) * (BN / TN);
    const int tid = threadIdx.x;
    const int tx = tid % (BN / TN);
    const int ty = tid / (BN / TN);
    const int rowBase = blockIdx.x * BM;
    const int colBase = blockIdx.y * BN;

    float acc[TM][TN];
    #pragma unroll
    for (int i = 0; i < TM; i++)
        #pragma unroll
        for (int j = 0; j < TN; j++) acc[i][j] = 0.f;

    for (int k0 = 0; k0 < K; k0 += BK) {
        // load A tile (transposed into As[k][m])
        #pragma unroll
        for (int i = tid; i < BM * BK / 4; i += nth) {
            int r = i / (BK / 4);
            int c4 = i % (BK / 4);
            int grow = rowBase + r;
            float4 v = make_float4(0.f, 0.f, 0.f, 0.f);
            if (grow < M) v = *(const float4*)(A + (size_t)grow * K + k0 + c4 * 4);
            As[c4 * 4 + 0][r] = v.x;
            As[c4 * 4 + 1][r] = v.y;
            As[c4 * 4 + 2][r] = v.z;
            As[c4 * 4 + 3][r] = v.w;
        }
        // load B tile
        #pragma unroll
        for (int i = tid; i < BK * BN / 4; i += nth) {
            int r = i / (BN / 4);
            int c4 = i % (BN / 4);
            *(float4*)&Bs[r][c4 * 4] =
                *(const float4*)(B + (size_t)(k0 + r) * Ncol + colBase + c4 * 4);
        }
        __syncthreads();
        #pragma unroll
        for (int kk = 0; kk < BK; ++kk) {
            float ra[TM], rb[TN];
            float4 a0 = *(const float4*)&As[kk][ty * TM];
            float4 a1 = *(const float4*)&As[kk][ty * TM + 4];
            ra[0] = a0.x; ra[1] = a0.y; ra[2] = a0.z; ra[3] = a0.w;
            ra[4] = a1.x; ra[5] = a1.y; ra[6] = a1.z; ra[7] = a1.w;
            float4 b4 = *(const float4*)&Bs[kk][tx * TN];
            rb[0] = b4.x; rb[1] = b4.y; rb[2] = b4.z; rb[3] = b4.w;
            #pragma unroll
            for (int i = 0; i < TM; i++)
                #pragma unroll
                for (int j = 0; j < TN; j++) acc[i][j] = fmaf(ra[i], rb[j], acc[i][j]);
        }
        __syncthreads();
    }
    #pragma unroll
    for (int i = 0; i < TM; i++) {
        int r = rowBase + ty * TM + i;
        if (r < M) {
            float4 v = make_float4(acc[i][0], acc[i][1], acc[i][2], acc[i][3]);
            *(float4*)(C + (size_t)r * Ncol + colBase + tx * TN) = v;
        }
    }
}

// ---------------- attention coefficients, layer 1 (H=4, C=64) ----------------
__global__ void attn1(const float* __restrict__ att_src, const float* __restrict__ att_dst) {
    int node = blockIdx.x * 8 + (threadIdx.x >> 5);
    if (node >= NN) return;
    int lane = threadIdx.x & 31;
    int head = lane >> 3;
    int sub = lane & 7;
    const float4* hp = (const float4*)(g_h1 + (size_t)node * 256 + lane * 8);
    float4 v0 = hp[0], v1 = hp[1];
    const float* asp = att_src + head * 64 + sub * 8;
    const float* adp = att_dst + head * 64 + sub * 8;
    float ps = v0.x * asp[0] + v0.y * asp[1] + v0.z * asp[2] + v0.w * asp[3]
             + v1.x * asp[4] + v1.y * asp[5] + v1.z * asp[6] + v1.w * asp[7];
    float pd = v0.x * adp[0] + v0.y * adp[1] + v0.z * adp[2] + v0.w * adp[3]
             + v1.x * adp[4] + v1.y * adp[5] + v1.z * adp[6] + v1.w * adp[7];
    #pragma unroll
    for (int o = 4; o; o >>= 1) {
        ps += __shfl_down_sync(0xffffffffu, ps, o, 8);
        pd += __shfl_down_sync(0xffffffffu, pd, o, 8);
    }
    if (sub == 0) {
        g_asrc1[node * 4 + head] = ps;
        g_adst1[node * 4 + head] = pd;
    }
}

// ---------------- CSR build ----------------
__global__ void init_cnt() {
    int i = blockIdx.x * blockDim.x + threadIdx.x;
    if (i < NN) g_cnt[i] = 1;  // self loop
}
__global__ void count_edges(const int* __restrict__ dst) {
    int e = blockIdx.x * blockDim.x + threadIdx.x;
    if (e < EE) atomicAdd(&g_cnt[dst[e]], 1);
}
__global__ void scan1() {
    __shared__ int wsum[32];
    int i = blockIdx.x * SCAN_BLK + threadIdx.x;
    int v = (i < NN) ? g_cnt[i] : 0;
    int lane = threadIdx.x & 31, wid = threadIdx.x >> 5;
    int incl = v;
    #pragma unroll
    for (int o = 1; o < 32; o <<= 1) {
        int t = __shfl_up_sync(0xffffffffu, incl, o);
        if (lane >= o) incl += t;
    }
    if (lane == 31) wsum[wid] = incl;
    __syncthreads();
    if (wid == 0) {
        int s = wsum[lane];
        #pragma unroll
        for (int o = 1; o < 32; o <<= 1) {
            int t = __shfl_up_sync(0xffffffffu, s, o);
            if (lane >= o) s += t;
        }
        wsum[lane] = s;
    }
    __syncthreads();
    int base = (wid > 0) ? wsum[wid - 1] : 0;
    incl += base;
    if (i < NN) g_rowptr[i] = incl - v;
    if (threadIdx.x == SCAN_BLK - 1) g_part[blockIdx.x] = incl;
}
__global__ void scan2() {
    if (threadIdx.x == 0) {
        int run = 0;
        for (int b = 0; b < NBLK_SCAN; b++) {
            int t = g_part[b];
            g_part[b] = run;
            run += t;
        }
        g_rowptr[NN] = run;
    }
}
__global__ void scan3() {
    int i = blockIdx.x * blockDim.x + threadIdx.x;
    if (i < NN) {
        int r = g_rowptr[i] + g_part[i >> 10];
        g_rowptr[i] = r;
        g_wpos[i] = r;
    }
}
__global__ void scatter_edges(const int* __restrict__ src, const int* __restrict__ dst) {
    int e = blockIdx.x * blockDim.x + threadIdx.x;
    if (e < EE) {
        int d = dst[e];
        int pos = atomicAdd(&g_wpos[d], 1);
        g_csr[pos] = src[e];
    } else if (e < EE + NN) {
        int i = e - EE;
        int pos = atomicAdd(&g_wpos[i], 1);
        g_csr[pos] = i;
    }
}

// ---------------- layer-1 aggregation: warp per dst node ----------------
__global__ __launch_bounds__(256) void aggregate1(const float* __restrict__ b1) {
    int node = blockIdx.x * 8 + (threadIdx.x >> 5);
    if (node >= NN) return;
    int lane = threadIdx.x & 31;
    int beg = g_rowptr[node], end = g_rowptr[node + 1];
    float4 ad = *(const float4*)(g_adst1 + node * 4);

    float m0 = -1e30f, m1 = -1e30f, m2 = -1e30f, m3 = -1e30f;
    for (int e = beg + lane; e < end; e += 32) {
        int s = g_csr[e];
        float4 as = *(const float4*)(g_asrc1 + s * 4);
        m0 = fmaxf(m0, lrelu(as.x + ad.x));
        m1 = fmaxf(m1, lrelu(as.y + ad.y));
        m2 = fmaxf(m2, lrelu(as.z + ad.z));
        m3 = fmaxf(m3, lrelu(as.w + ad.w));
    }
    m0 = warpMax(m0); m1 = warpMax(m1); m2 = warpMax(m2); m3 = warpMax(m3);

    float s0 = 0.f, s1 = 0.f, s2 = 0.f, s3 = 0.f;
    for (int e = beg + lane; e < end; e += 32) {
        int s = g_csr[e];
        float4 as = *(const float4*)(g_asrc1 + s * 4);
        s0 += expf(lrelu(as.x + ad.x) - m0);
        s1 += expf(lrelu(as.y + ad.y) - m1);
        s2 += expf(lrelu(as.z + ad.z) - m2);
        s3 += expf(lrelu(as.w + ad.w) - m3);
    }
    s0 = warpSum(s0); s1 = warpSum(s1); s2 = warpSum(s2); s3 = warpSum(s3);
    float i0 = 1.f / (s0 + 1e-16f), i1 = 1.f / (s1 + 1e-16f);
    float i2 = 1.f / (s2 + 1e-16f), i3 = 1.f / (s3 + 1e-16f);

    int head = lane >> 3;
    float mh  = head < 2 ? (head == 0 ? m0 : m1) : (head == 2 ? m2 : m3);
    float ih  = head < 2 ? (head == 0 ? i0 : i1) : (head == 2 ? i2 : i3);
    float adh = head < 2 ? (head == 0 ? ad.x : ad.y) : (head == 2 ? ad.z : ad.w);

    float acc[8];
    #pragma unroll
    for (int k = 0; k < 8; k++) acc[k] = 0.f;

    for (int e = beg; e < end; ++e) {
        int s = g_csr[e];
        float w = expf(lrelu(g_asrc1[s * 4 + head] + adh) - mh) * ih;
        const float4* p = (const float4*)(g_h1 + (size_t)s * 256 + lane * 8);
        float4 v0 = p[0], v1 = p[1];
        acc[0] = fmaf(w, v0.x, acc[0]); acc[1] = fmaf(w, v0.y, acc[1]);
        acc[2] = fmaf(w, v0.z, acc[2]); acc[3] = fmaf(w, v0.w, acc[3]);
        acc[4] = fmaf(w, v1.x, acc[4]); acc[5] = fmaf(w, v1.y, acc[5]);
        acc[6] = fmaf(w, v1.z, acc[6]); acc[7] = fmaf(w, v1.w, acc[7]);
    }
    size_t ob = (size_t)node * 256 + lane * 8;
    const float* bb = b1 + lane * 8;
    #pragma unroll
    for (int k = 0; k < 8; k++) {
        float r = acc[k] + bb[k];
        g_e1[ob + k] = r > 0.f ? r : (expf(r) - 1.f);  // ELU
    }
}

// ---------------- attention coefficients, layer 2 (H=1, C=64) ----------------
__global__ void attn2(const float* __restrict__ att_src, const float* __restrict__ att_dst) {
    int node = blockIdx.x * 8 + (threadIdx.x >> 5);
    if (node >= NN) return;
    int lane = threadIdx.x & 31;
    float2 v = *(const float2*)(g_h2 + (size_t)node * 64 + lane * 2);
    float ps = v.x * att_src[lane * 2] + v.y * att_src[lane * 2 + 1];
    float pd = v.x * att_dst[lane * 2] + v.y * att_dst[lane * 2 + 1];
    ps = warpSum(ps);
    pd = warpSum(pd);
    if (lane == 0) {
        g_asrc2[node] = ps;
        g_adst2[node] = pd;
    }
}

// ---------------- layer-2 aggregation ----------------
__global__ __launch_bounds__(256) void aggregate2(const float* __restrict__ b2) {
    int node = blockIdx.x * 8 + (threadIdx.x >> 5);
    if (node >= NN) return;
    int lane = threadIdx.x & 31;
    int beg = g_rowptr[node], end = g_rowptr[node + 1];
    float adv = g_adst2[node];

    float m = -1e30f;
    for (int e = beg + lane; e < end; e += 32)
        m = fmaxf(m, lrelu(g_asrc2[g_csr[e]] + adv));
    m = warpMax(m);
    float sm = 0.f;
    for (int e = beg + lane; e < end; e += 32)
        sm += expf(lrelu(g_asrc2[g_csr[e]] + adv) - m);
    sm = warpSum(sm);
    float inv = 1.f / (sm + 1e-16f);

    float a0 = 0.f, a1 = 0.f;
    for (int e = beg; e < end; ++e) {
        int s = g_csr[e];
        float w = expf(lrelu(g_asrc2[s] + adv) - m) * inv;
        float2 v = *(const float2*)(g_h2 + (size_t)s * 64 + lane * 2);
        a0 = fmaf(w, v.x, a0);
        a1 = fmaf(w, v.y, a1);
    }
    g_o2[(size_t)node * 64 + lane * 2]     = a0 + b2[lane * 2];
    g_o2[(size_t)node * 64 + lane * 2 + 1] = a1 + b2[lane * 2 + 1];
}

// ---------------- global mean pool (batch is sorted) ----------------
__device__ __forceinline__ int lower_bound_i(const int* b, int n, int v) {
    int lo = 0, hi = n;
    while (lo < hi) {
        int mid = (lo + hi) >> 1;
        if (b[mid] < v) lo = mid + 1; else hi = mid;
    }
    return lo;
}
__global__ void pool(const int* __restrict__ batch) {
    __shared__ float part[256];
    __shared__ int sb, se;
    int g = blockIdx.x;
    if (threadIdx.x == 0) {
        sb = lower_bound_i(batch, NN, g);
        se = lower_bound_i(batch, NN, g + 1);
    }
    __syncthreads();
    int c = threadIdx.x & 63, q = threadIdx.x >> 6;
    float s = 0.f;
    for (int i = sb + q; i < se; i += 4) s += g_o2[(size_t)i * 64 + c];
    part[threadIdx.x] = s;
    __syncthreads();
    if (q == 0) {
        float t = part[c] + part[c + 64] + part[c + 128] + part[c + 192];
        float cnt = (float)(se - sb);
        g_emb[g * 64 + c] = t / fmaxf(cnt, 1.f);
    }
}

// ---------------- final MLP ----------------
__global__ void mlp(const float* __restrict__ W3, const float* __restrict__ b3,
                    const float* __restrict__ W4, const float* __restrict__ b4,
                    float* __restrict__ out) {
    __shared__ float w3[64 * 32], w4[64], bb3[32], bb4[2];
    int t = threadIdx.x;
    for (int i = t; i < 2048; i += 64) w3[i] = W3[i];
    w4[t] = W4[t];
    if (t < 32) bb3[t] = b3[t];
    if (t < 2) bb4[t] = b4[t];
    __syncthreads();
    float e[64];
    #pragma unroll
    for (int k = 0; k < 64; k++) e[k] = g_emb[t * 64 + k];
    float l0 = bb4[0], l1 = bb4[1];
    #pragma unroll 4
    for (int j = 0; j < 32; j++) {
        float z = bb3[j];
        #pragma unroll
        for (int k = 0; k < 64; k++) z = fmaf(e[k], w3[k * 32 + j], z);
        z = fmaxf(z, 0.f);
        l0 = fmaf(z, w4[j * 2], l0);
        l1 = fmaf(z, w4[j * 2 + 1], l1);
    }
    out[t * 2] = l0;
    out[t * 2 + 1] = l1;
}

// ---------------- launch ----------------
extern "C" void kernel_launch(void* const* d_in, const int* in_sizes, int n_in,
                              void* d_out, int out_size) {
    const float* x = (const float*)d_in[0];
    const int* ei = (const int*)d_in[1];
    const int* batch = (const int*)d_in[2];
    const float* W1 = (const float*)d_in[3];
    const float* as1 = (const float*)d_in[4];
    const float* ad1 = (const float*)d_in[5];
    const float* b1 = (const float*)d_in[6];
    const float* W2 = (const float*)d_in[7];
    const float* as2 = (const float*)d_in[8];
    const float* ad2 = (const float*)d_in[9];
    const float* b2 = (const float*)d_in[10];
    const float* W3 = (const float*)d_in[11];
    const float* b3 = (const float*)d_in[12];
    const float* W4 = (const float*)d_in[13];
    const float* b4 = (const float*)d_in[14];
    float* out = (float*)d_out;

    const int* e_src = ei;
    const int* e_dst = ei + EE;

    void* p;
    cudaGetSymbolAddress(&p, g_h1);  float* h1 = (float*)p;
    cudaGetSymbolAddress(&p, g_e1);  float* e1 = (float*)p;
    cudaGetSymbolAddress(&p, g_h2);  float* h2 = (float*)p;

    const int agg_blocks = NN / 8;  // 12500, exact

    // GEMM1: h1 = x @ W1  [100000,256]
    sgemm<128, 64, 16, 8, 4><<<dim3(782, 4), 256>>>(x, W1, h1, NN, 256, 256);
    // attention coefficients layer 1
    attn1<<<agg_blocks, 256>>>(as1, ad1);
    // CSR build
    init_cnt<<<(NN + 255) / 256, 256>>>();
    count_edges<<<(EE + 255) / 256, 256>>>(e_dst);
    scan1<<<NBLK_SCAN, SCAN_BLK>>>();
    scan2<<<1, 32>>>();
    scan3<<<(NN + 255) / 256, 256>>>();
    scatter_edges<<<(EE + NN + 255) / 256, 256>>>(e_src, e_dst);
    // layer-1 softmax-aggregate + ELU
    aggregate1<<<agg_blocks, 256>>>(b1);
    // GEMM2: h2 = e1 @ W2  [100000,64]
    sgemm<128, 64, 16, 8, 4><<<dim3(782, 1), 256>>>(e1, W2, h2, NN, 256, 64);
    attn2<<<agg_blocks, 256>>>(as2, ad2);
    aggregate2<<<agg_blocks, 256>>>(b2);
    // mean pool + MLP head
    pool<<<GG, 256>>>(batch);
    mlp<<<1, 64>>>(W3, b3, W4, b4, out);
}

// round 4
// speedup vs baseline: 1.3658x; 1.3658x over previous
#include <cuda_runtime.h>
#include <stdint.h>
#include <math.h>

#define NN 100000
#define EE 1600000
#define GG 64
#define SCAN_BLK 1024
#define NBLK_SCAN ((NN + SCAN_BLK - 1) / SCAN_BLK)   // 98

// ---------------- scratch (device globals; no allocation) ----------------
__device__ __align__(16) float g_h1[(size_t)NN * 256];   // x @ W1
__device__ __align__(16) float g_e1[(size_t)NN * 256];   // elu(aggregate1)
__device__ __align__(16) float g_h2[(size_t)NN * 64];    // e1 @ W2
__device__ __align__(16) float g_o2[(size_t)NN * 64];    // aggregate2
__device__ __align__(16) float g_asrc1[NN * 4];
__device__ __align__(16) float g_adst1[NN * 4];
__device__ float g_asrc2[NN];
__device__ float g_adst2[NN];
__device__ int   g_cnt[NN];
__device__ int   g_rowptr[NN + 1];
__device__ int   g_wpos[NN];
__device__ int   g_csr[EE + NN];
__device__ int   g_part[NBLK_SCAN + 8];
__device__ float g_emb[GG * 64];

// ---------------- helpers ----------------
__device__ __forceinline__ float warpMax(float v) {
    #pragma unroll
    for (int o = 16; o; o >>= 1) v = fmaxf(v, __shfl_xor_sync(0xffffffffu, v, o));
    return v;
}
__device__ __forceinline__ float warpSum(float v) {
    #pragma unroll
    for (int o = 16; o; o >>= 1) v += __shfl_xor_sync(0xffffffffu, v, o);
    return v;
}
__device__ __forceinline__ float lrelu(float a) { return a > 0.f ? a : 0.2f * a; }
__device__ __forceinline__ float to_tf32(float f) {
    uint32_t u;
    asm("cvt.rna.tf32.f32 %0, %1;" : "=r"(u) : "f"(f));
    return __uint_as_float(u);
}

// ---------------- TF32 tensor-core GEMM: C[M,Ncol] = A[M,K] @ B[K,Ncol] ----
// BM=128, BN=64, BK=16. 8 warps: 4 along M x 2 along N, warp tile 32x32.
// mma.sync.aligned.m16n8k8.row.col.f32.tf32.tf32.f32
#define PAD_A 4
#define PAD_B 8
__global__ __launch_bounds__(256)
void gemm_tf32(const float* __restrict__ A, const float* __restrict__ B,
               float* __restrict__ C, int M, int K, int Ncol) {
    const int BM = 128, BN = 64, BK = 16;
    __shared__ float As[128][BK + PAD_A];   // 10 KB
    __shared__ float Bs[BK][BN + PAD_B];    // 4.5 KB

    const int tid = threadIdx.x;
    const int warp = tid >> 5, lane = tid & 31;
    const int warpM = warp & 3, warpN = warp >> 2;    // 4 x 2
    const int rowBase = blockIdx.x * BM;
    const int colBase = blockIdx.y * BN;
    const int gid = lane >> 2;    // 0..7
    const int tig = lane & 3;     // 0..3

    float c[2][4][4];
    #pragma unroll
    for (int mt = 0; mt < 2; mt++)
        #pragma unroll
        for (int nt = 0; nt < 4; nt++)
            #pragma unroll
            for (int r = 0; r < 4; r++) c[mt][nt][r] = 0.f;

    for (int k0 = 0; k0 < K; k0 += BK) {
        // A tile: 128 rows x 16 k = 512 float4, 2 per thread
        #pragma unroll
        for (int it = 0; it < 2; it++) {
            int i = tid + it * 256;
            int r = i >> 2, q = i & 3;
            float4 v = make_float4(0.f, 0.f, 0.f, 0.f);
            if (rowBase + r < M)
                v = *(const float4*)(A + (size_t)(rowBase + r) * K + k0 + q * 4);
            As[r][q * 4 + 0] = to_tf32(v.x);
            As[r][q * 4 + 1] = to_tf32(v.y);
            As[r][q * 4 + 2] = to_tf32(v.z);
            As[r][q * 4 + 3] = to_tf32(v.w);
        }
        // B tile: 16 x 64 = 256 float4, 1 per thread
        {
            int r = tid >> 4, q = tid & 15;
            float4 v = *(const float4*)(B + (size_t)(k0 + r) * Ncol + colBase + q * 4);
            Bs[r][q * 4 + 0] = to_tf32(v.x);
            Bs[r][q * 4 + 1] = to_tf32(v.y);
            Bs[r][q * 4 + 2] = to_tf32(v.z);
            Bs[r][q * 4 + 3] = to_tf32(v.w);
        }
        __syncthreads();

        #pragma unroll
        for (int ks = 0; ks < BK; ks += 8) {
            uint32_t a[2][4], b[4][2];
            #pragma unroll
            for (int mt = 0; mt < 2; mt++) {
                int row = warpM * 32 + mt * 16 + gid;
                a[mt][0] = __float_as_uint(As[row][ks + tig]);
                a[mt][1] = __float_as_uint(As[row + 8][ks + tig]);
                a[mt][2] = __float_as_uint(As[row][ks + tig + 4]);
                a[mt][3] = __float_as_uint(As[row + 8][ks + tig + 4]);
            }
            #pragma unroll
            for (int nt = 0; nt < 4; nt++) {
                int col = warpN * 32 + nt * 8 + gid;
                b[nt][0] = __float_as_uint(Bs[ks + tig][col]);
                b[nt][1] = __float_as_uint(Bs[ks + tig + 4][col]);
            }
            #pragma unroll
            for (int mt = 0; mt < 2; mt++)
                #pragma unroll
                for (int nt = 0; nt < 4; nt++) {
                    asm volatile(
                        "mma.sync.aligned.m16n8k8.row.col.f32.tf32.tf32.f32 "
                        "{%0,%1,%2,%3}, {%4,%5,%6,%7}, {%8,%9}, {%0,%1,%2,%3};"
                        : "+f"(c[mt][nt][0]), "+f"(c[mt][nt][1]),
                          "+f"(c[mt][nt][2]), "+f"(c[mt][nt][3])
                        : "r"(a[mt][0]), "r"(a[mt][1]), "r"(a[mt][2]), "r"(a[mt][3]),
                          "r"(b[nt][0]), "r"(b[nt][1]));
                }
        }
        __syncthreads();
    }

    #pragma unroll
    for (int mt = 0; mt < 2; mt++) {
        int row0 = rowBase + warpM * 32 + mt * 16 + gid;
        #pragma unroll
        for (int nt = 0; nt < 4; nt++) {
            int col = colBase + warpN * 32 + nt * 8 + tig * 2;
            if (row0 < M)
                *(float2*)(C + (size_t)row0 * Ncol + col) =
                    make_float2(c[mt][nt][0], c[mt][nt][1]);
            if (row0 + 8 < M)
                *(float2*)(C + (size_t)(row0 + 8) * Ncol + col) =
                    make_float2(c[mt][nt][2], c[mt][nt][3]);
        }
    }
}

// ---------------- attention coefficients, layer 1 (H=4, C=64) ----------------
__global__ void attn1(const float* __restrict__ att_src, const float* __restrict__ att_dst) {
    int node = blockIdx.x * 8 + (threadIdx.x >> 5);
    if (node >= NN) return;
    int lane = threadIdx.x & 31;
    int head = lane >> 3;
    int sub = lane & 7;
    const float4* hp = (const float4*)(g_h1 + (size_t)node * 256 + lane * 8);
    float4 v0 = hp[0], v1 = hp[1];
    const float* asp = att_src + head * 64 + sub * 8;
    const float* adp = att_dst + head * 64 + sub * 8;
    float ps = v0.x * asp[0] + v0.y * asp[1] + v0.z * asp[2] + v0.w * asp[3]
             + v1.x * asp[4] + v1.y * asp[5] + v1.z * asp[6] + v1.w * asp[7];
    float pd = v0.x * adp[0] + v0.y * adp[1] + v0.z * adp[2] + v0.w * adp[3]
             + v1.x * adp[4] + v1.y * adp[5] + v1.z * adp[6] + v1.w * adp[7];
    #pragma unroll
    for (int o = 4; o; o >>= 1) {
        ps += __shfl_down_sync(0xffffffffu, ps, o, 8);
        pd += __shfl_down_sync(0xffffffffu, pd, o, 8);
    }
    if (sub == 0) {
        g_asrc1[node * 4 + head] = ps;
        g_adst1[node * 4 + head] = pd;
    }
}

// ---------------- CSR build ----------------
__global__ void init_cnt() {
    int i = blockIdx.x * blockDim.x + threadIdx.x;
    if (i < NN) g_cnt[i] = 1;  // self loop
}
__global__ void count_edges(const int* __restrict__ dst) {
    int e = blockIdx.x * blockDim.x + threadIdx.x;
    if (e < EE) atomicAdd(&g_cnt[dst[e]], 1);
}
__global__ void scan1() {
    __shared__ int wsum[32];
    int i = blockIdx.x * SCAN_BLK + threadIdx.x;
    int v = (i < NN) ? g_cnt[i] : 0;
    int lane = threadIdx.x & 31, wid = threadIdx.x >> 5;
    int incl = v;
    #pragma unroll
    for (int o = 1; o < 32; o <<= 1) {
        int t = __shfl_up_sync(0xffffffffu, incl, o);
        if (lane >= o) incl += t;
    }
    if (lane == 31) wsum[wid] = incl;
    __syncthreads();
    if (wid == 0) {
        int s = wsum[lane];
        #pragma unroll
        for (int o = 1; o < 32; o <<= 1) {
            int t = __shfl_up_sync(0xffffffffu, s, o);
            if (lane >= o) s += t;
        }
        wsum[lane] = s;
    }
    __syncthreads();
    int base = (wid > 0) ? wsum[wid - 1] : 0;
    incl += base;
    if (i < NN) g_rowptr[i] = incl - v;
    if (threadIdx.x == SCAN_BLK - 1) g_part[blockIdx.x] = incl;
}
__global__ void scan2() {
    if (threadIdx.x == 0) {
        int run = 0;
        for (int b = 0; b < NBLK_SCAN; b++) {
            int t = g_part[b];
            g_part[b] = run;
            run += t;
        }
        g_rowptr[NN] = run;
    }
}
__global__ void scan3() {
    int i = blockIdx.x * blockDim.x + threadIdx.x;
    if (i < NN) {
        int r = g_rowptr[i] + g_part[i >> 10];
        g_rowptr[i] = r;
        g_wpos[i] = r;
    }
}
__global__ void scatter_edges(const int* __restrict__ src, const int* __restrict__ dst) {
    int e = blockIdx.x * blockDim.x + threadIdx.x;
    if (e < EE) {
        int d = dst[e];
        int pos = atomicAdd(&g_wpos[d], 1);
        g_csr[pos] = src[e];
    } else if (e < EE + NN) {
        int i = e - EE;
        int pos = atomicAdd(&g_wpos[i], 1);
        g_csr[pos] = i;
    }
}

// ---------------- layer-1 aggregation: warp per dst node ----------------
__global__ __launch_bounds__(256) void aggregate1(const float* __restrict__ b1) {
    int node = blockIdx.x * 8 + (threadIdx.x >> 5);
    if (node >= NN) return;
    int lane = threadIdx.x & 31;
    int beg = g_rowptr[node], end = g_rowptr[node + 1];
    float4 ad = *(const float4*)(g_adst1 + node * 4);

    float m0 = -1e30f, m1 = -1e30f, m2 = -1e30f, m3 = -1e30f;
    for (int e = beg + lane; e < end; e += 32) {
        int s = g_csr[e];
        float4 as = *(const float4*)(g_asrc1 + s * 4);
        m0 = fmaxf(m0, lrelu(as.x + ad.x));
        m1 = fmaxf(m1, lrelu(as.y + ad.y));
        m2 = fmaxf(m2, lrelu(as.z + ad.z));
        m3 = fmaxf(m3, lrelu(as.w + ad.w));
    }
    m0 = warpMax(m0); m1 = warpMax(m1); m2 = warpMax(m2); m3 = warpMax(m3);

    float s0 = 0.f, s1 = 0.f, s2 = 0.f, s3 = 0.f;
    for (int e = beg + lane; e < end; e += 32) {
        int s = g_csr[e];
        float4 as = *(const float4*)(g_asrc1 + s * 4);
        s0 += expf(lrelu(as.x + ad.x) - m0);
        s1 += expf(lrelu(as.y + ad.y) - m1);
        s2 += expf(lrelu(as.z + ad.z) - m2);
        s3 += expf(lrelu(as.w + ad.w) - m3);
    }
    s0 = warpSum(s0); s1 = warpSum(s1); s2 = warpSum(s2); s3 = warpSum(s3);
    float i0 = 1.f / (s0 + 1e-16f), i1 = 1.f / (s1 + 1e-16f);
    float i2 = 1.f / (s2 + 1e-16f), i3 = 1.f / (s3 + 1e-16f);

    int head = lane >> 3;
    float mh  = head < 2 ? (head == 0 ? m0 : m1) : (head == 2 ? m2 : m3);
    float ih  = head < 2 ? (head == 0 ? i0 : i1) : (head == 2 ? i2 : i3);
    float adh = head < 2 ? (head == 0 ? ad.x : ad.y) : (head == 2 ? ad.z : ad.w);

    float acc[8];
    #pragma unroll
    for (int k = 0; k < 8; k++) acc[k] = 0.f;

    for (int e = beg; e < end; ++e) {
        int s = g_csr[e];
        float w = expf(lrelu(g_asrc1[s * 4 + head] + adh) - mh) * ih;
        const float4* p = (const float4*)(g_h1 + (size_t)s * 256 + lane * 8);
        float4 v0 = p[0], v1 = p[1];
        acc[0] = fmaf(w, v0.x, acc[0]); acc[1] = fmaf(w, v0.y, acc[1]);
        acc[2] = fmaf(w, v0.z, acc[2]); acc[3] = fmaf(w, v0.w, acc[3]);
        acc[4] = fmaf(w, v1.x, acc[4]); acc[5] = fmaf(w, v1.y, acc[5]);
        acc[6] = fmaf(w, v1.z, acc[6]); acc[7] = fmaf(w, v1.w, acc[7]);
    }
    size_t ob = (size_t)node * 256 + lane * 8;
    const float* bb = b1 + lane * 8;
    #pragma unroll
    for (int k = 0; k < 8; k++) {
        float r = acc[k] + bb[k];
        g_e1[ob + k] = r > 0.f ? r : (expf(r) - 1.f);  // ELU
    }
}

// ---------------- attention coefficients, layer 2 (H=1, C=64) ----------------
__global__ void attn2(const float* __restrict__ att_src, const float* __restrict__ att_dst) {
    int node = blockIdx.x * 8 + (threadIdx.x >> 5);
    if (node >= NN) return;
    int lane = threadIdx.x & 31;
    float2 v = *(const float2*)(g_h2 + (size_t)node * 64 + lane * 2);
    float ps = v.x * att_src[lane * 2] + v.y * att_src[lane * 2 + 1];
    float pd = v.x * att_dst[lane * 2] + v.y * att_dst[lane * 2 + 1];
    ps = warpSum(ps);
    pd = warpSum(pd);
    if (lane == 0) {
        g_asrc2[node] = ps;
        g_adst2[node] = pd;
    }
}

// ---------------- layer-2 aggregation ----------------
__global__ __launch_bounds__(256) void aggregate2(const float* __restrict__ b2) {
    int node = blockIdx.x * 8 + (threadIdx.x >> 5);
    if (node >= NN) return;
    int lane = threadIdx.x & 31;
    int beg = g_rowptr[node], end = g_rowptr[node + 1];
    float adv = g_adst2[node];

    float m = -1e30f;
    for (int e = beg + lane; e < end; e += 32)
        m = fmaxf(m, lrelu(g_asrc2[g_csr[e]] + adv));
    m = warpMax(m);
    float sm = 0.f;
    for (int e = beg + lane; e < end; e += 32)
        sm += expf(lrelu(g_asrc2[g_csr[e]] + adv) - m);
    sm = warpSum(sm);
    float inv = 1.f / (sm + 1e-16f);

    float a0 = 0.f, a1 = 0.f;
    for (int e = beg; e < end; ++e) {
        int s = g_csr[e];
        float w = expf(lrelu(g_asrc2[s] + adv) - m) * inv;
        float2 v = *(const float2*)(g_h2 + (size_t)s * 64 + lane * 2);
        a0 = fmaf(w, v.x, a0);
        a1 = fmaf(w, v.y, a1);
    }
    g_o2[(size_t)node * 64 + lane * 2]     = a0 + b2[lane * 2];
    g_o2[(size_t)node * 64 + lane * 2 + 1] = a1 + b2[lane * 2 + 1];
}

// ---------------- global mean pool (batch is sorted) ----------------
__device__ __forceinline__ int lower_bound_i(const int* b, int n, int v) {
    int lo = 0, hi = n;
    while (lo < hi) {
        int mid = (lo + hi) >> 1;
        if (b[mid] < v) lo = mid + 1; else hi = mid;
    }
    return lo;
}
__global__ void pool(const int* __restrict__ batch) {
    __shared__ float part[256];
    __shared__ int sb, se;
    int g = blockIdx.x;
    if (threadIdx.x == 0) {
        sb = lower_bound_i(batch, NN, g);
        se = lower_bound_i(batch, NN, g + 1);
    }
    __syncthreads();
    int c = threadIdx.x & 63, q = threadIdx.x >> 6;
    float s = 0.f;
    for (int i = sb + q; i < se; i += 4) s += g_o2[(size_t)i * 64 + c];
    part[threadIdx.x] = s;
    __syncthreads();
    if (q == 0) {
        float t = part[c] + part[c + 64] + part[c + 128] + part[c + 192];
        float cnt = (float)(se - sb);
        g_emb[g * 64 + c] = t / fmaxf(cnt, 1.f);
    }
}

// ---------------- final MLP ----------------
__global__ void mlp(const float* __restrict__ W3, const float* __restrict__ b3,
                    const float* __restrict__ W4, const float* __restrict__ b4,
                    float* __restrict__ out) {
    __shared__ float w3[64 * 32], w4[64], bb3[32], bb4[2];
    int t = threadIdx.x;
    for (int i = t; i < 2048; i += 64) w3[i] = W3[i];
    w4[t] = W4[t];
    if (t < 32) bb3[t] = b3[t];
    if (t < 2) bb4[t] = b4[t];
    __syncthreads();
    float e[64];
    #pragma unroll
    for (int k = 0; k < 64; k++) e[k] = g_emb[t * 64 + k];
    float l0 = bb4[0], l1 = bb4[1];
    #pragma unroll 4
    for (int j = 0; j < 32; j++) {
        float z = bb3[j];
        #pragma unroll
        for (int k = 0; k < 64; k++) z = fmaf(e[k], w3[k * 32 + j], z);
        z = fmaxf(z, 0.f);
        l0 = fmaf(z, w4[j * 2], l0);
        l1 = fmaf(z, w4[j * 2 + 1], l1);
    }
    out[t * 2] = l0;
    out[t * 2 + 1] = l1;
}

// ---------------- launch ----------------
extern "C" void kernel_launch(void* const* d_in, const int* in_sizes, int n_in,
                              void* d_out, int out_size) {
    const float* x = (const float*)d_in[0];
    const int* ei = (const int*)d_in[1];
    const int* batch = (const int*)d_in[2];
    const float* W1 = (const float*)d_in[3];
    const float* as1 = (const float*)d_in[4];
    const float* ad1 = (const float*)d_in[5];
    const float* b1 = (const float*)d_in[6];
    const float* W2 = (const float*)d_in[7];
    const float* as2 = (const float*)d_in[8];
    const float* ad2 = (const float*)d_in[9];
    const float* b2 = (const float*)d_in[10];
    const float* W3 = (const float*)d_in[11];
    const float* b3 = (const float*)d_in[12];
    const float* W4 = (const float*)d_in[13];
    const float* b4 = (const float*)d_in[14];
    float* out = (float*)d_out;

    const int* e_src = ei;
    const int* e_dst = ei + EE;

    void* p;
    cudaGetSymbolAddress(&p, g_h1);  float* h1 = (float*)p;
    cudaGetSymbolAddress(&p, g_e1);  float* e1 = (float*)p;
    cudaGetSymbolAddress(&p, g_h2);  float* h2 = (float*)p;

    const int agg_blocks = NN / 8;  // 12500, exact

    // GEMM1: h1 = x @ W1  [100000,256] (tf32 tensor cores)
    gemm_tf32<<<dim3(782, 4), 256>>>(x, W1, h1, NN, 256, 256);
    // attention coefficients layer 1
    attn1<<<agg_blocks, 256>>>(as1, ad1);
    // CSR build
    init_cnt<<<(NN + 255) / 256, 256>>>();
    count_edges<<<(EE + 255) / 256, 256>>>(e_dst);
    scan1<<<NBLK_SCAN, SCAN_BLK>>>();
    scan2<<<1, 32>>>();
    scan3<<<(NN + 255) / 256, 256>>>();
    scatter_edges<<<(EE + NN + 255) / 256, 256>>>(e_src, e_dst);
    // layer-1 softmax-aggregate + ELU
    aggregate1<<<agg_blocks, 256>>>(b1);
    // GEMM2: h2 = e1 @ W2  [100000,64] (tf32 tensor cores)
    gemm_tf32<<<dim3(782, 1), 256>>>(e1, W2, h2, NN, 256, 64);
    attn2<<<agg_blocks, 256>>>(as2, ad2);
    aggregate2<<<agg_blocks, 256>>>(b2);
    // mean pool + MLP head
    pool<<<GG, 256>>>(batch);
    mlp<<<1, 64>>>(W3, b3, W4, b4, out);
}

// round 5
// speedup vs baseline: 1.5999x; 1.1714x over previous
#include <cuda_runtime.h>
#include <cuda_fp16.h>
#include <stdint.h>
#include <math.h>

#define NN 100000
#define EE 1600000
#define GG 64
#define SCAN_BLK 1024
#define NBLK_SCAN ((NN + SCAN_BLK - 1) / SCAN_BLK)   // 98

// ---------------- scratch (device globals; no allocation) ----------------
__device__ __align__(16) __half g_h1h[(size_t)NN * 256];  // x @ W1 (fp16)
__device__ __align__(16) __half g_e1h[(size_t)NN * 256];  // elu(aggregate1) (fp16)
__device__ __align__(16) __half g_h2h[(size_t)NN * 64];   // e1 @ W2 (fp16)
__device__ __align__(16) float g_o2[(size_t)NN * 64];     // aggregate2 (fp32)
__device__ __align__(16) float g_asrc1[NN * 4];
__device__ __align__(16) float g_adst1[NN * 4];
__device__ float g_asrc2[NN];
__device__ float g_adst2[NN];
__device__ int   g_cnt[NN];
__device__ int   g_rowptr[NN + 1];
__device__ int   g_wpos[NN];
__device__ int   g_csr[EE + NN];
__device__ int   g_part[NBLK_SCAN + 8];
__device__ float g_emb[GG * 64];

// ---------------- helpers ----------------
__device__ __forceinline__ float warpMax(float v) {
    #pragma unroll
    for (int o = 16; o; o >>= 1) v = fmaxf(v, __shfl_xor_sync(0xffffffffu, v, o));
    return v;
}
__device__ __forceinline__ float warpSum(float v) {
    #pragma unroll
    for (int o = 16; o; o >>= 1) v += __shfl_xor_sync(0xffffffffu, v, o);
    return v;
}
__device__ __forceinline__ float lrelu(float a) { return a > 0.f ? a : 0.2f * a; }
__device__ __forceinline__ float to_tf32(float f) {
    uint32_t u;
    asm("cvt.rna.tf32.f32 %0, %1;" : "=r"(u) : "f"(f));
    return __uint_as_float(u);
}

// ---------------- TF32 tensor-core GEMM: C[M,Ncol] = A[M,K] @ B[K,Ncol] ----
// A is fp32 or fp16 (template), B fp32, C fp16.
// BM=128, BN=64, BK=16. 8 warps: 4 along M x 2 along N, warp tile 32x32.
#define PAD_A 4
#define PAD_B 8
template <bool HALF_A>
__global__ __launch_bounds__(256)
void gemm_tf32(const void* __restrict__ Av, const float* __restrict__ B,
               __half* __restrict__ C, int M, int K, int Ncol) {
    const int BM = 128, BN = 64, BK = 16;
    __shared__ float As[128][BK + PAD_A];
    __shared__ float Bs[BK][BN + PAD_B];

    const int tid = threadIdx.x;
    const int warp = tid >> 5, lane = tid & 31;
    const int warpM = warp & 3, warpN = warp >> 2;
    const int rowBase = blockIdx.x * BM;
    const int colBase = blockIdx.y * BN;
    const int gid = lane >> 2;
    const int tig = lane & 3;

    float c[2][4][4];
    #pragma unroll
    for (int mt = 0; mt < 2; mt++)
        #pragma unroll
        for (int nt = 0; nt < 4; nt++)
            #pragma unroll
            for (int r = 0; r < 4; r++) c[mt][nt][r] = 0.f;

    for (int k0 = 0; k0 < K; k0 += BK) {
        if (HALF_A) {
            // 128 rows x 16 halves = 2048 halves; 2 threads/row, 8 halves each
            const __half* A = (const __half*)Av;
            int r = tid >> 1, off = (tid & 1) * 8;
            uint4 raw = make_uint4(0u, 0u, 0u, 0u);
            if (rowBase + r < M)
                raw = *(const uint4*)(A + (size_t)(rowBase + r) * K + k0 + off);
            const __half2* hp = (const __half2*)&raw;
            #pragma unroll
            for (int q = 0; q < 4; q++) {
                float2 f = __half22float2(hp[q]);
                As[r][off + q * 2 + 0] = to_tf32(f.x);
                As[r][off + q * 2 + 1] = to_tf32(f.y);
            }
        } else {
            const float* A = (const float*)Av;
            #pragma unroll
            for (int it = 0; it < 2; it++) {
                int i = tid + it * 256;
                int r = i >> 2, q = i & 3;
                float4 v = make_float4(0.f, 0.f, 0.f, 0.f);
                if (rowBase + r < M)
                    v = *(const float4*)(A + (size_t)(rowBase + r) * K + k0 + q * 4);
                As[r][q * 4 + 0] = to_tf32(v.x);
                As[r][q * 4 + 1] = to_tf32(v.y);
                As[r][q * 4 + 2] = to_tf32(v.z);
                As[r][q * 4 + 3] = to_tf32(v.w);
            }
        }
        // B tile: 16 x 64 = 256 float4, 1 per thread
        {
            int r = tid >> 4, q = tid & 15;
            float4 v = *(const float4*)(B + (size_t)(k0 + r) * Ncol + colBase + q * 4);
            Bs[r][q * 4 + 0] = to_tf32(v.x);
            Bs[r][q * 4 + 1] = to_tf32(v.y);
            Bs[r][q * 4 + 2] = to_tf32(v.z);
            Bs[r][q * 4 + 3] = to_tf32(v.w);
        }
        __syncthreads();

        #pragma unroll
        for (int ks = 0; ks < BK; ks += 8) {
            uint32_t a[2][4], b[4][2];
            #pragma unroll
            for (int mt = 0; mt < 2; mt++) {
                int row = warpM * 32 + mt * 16 + gid;
                a[mt][0] = __float_as_uint(As[row][ks + tig]);
                a[mt][1] = __float_as_uint(As[row + 8][ks + tig]);
                a[mt][2] = __float_as_uint(As[row][ks + tig + 4]);
                a[mt][3] = __float_as_uint(As[row + 8][ks + tig + 4]);
            }
            #pragma unroll
            for (int nt = 0; nt < 4; nt++) {
                int col = warpN * 32 + nt * 8 + gid;
                b[nt][0] = __float_as_uint(Bs[ks + tig][col]);
                b[nt][1] = __float_as_uint(Bs[ks + tig + 4][col]);
            }
            #pragma unroll
            for (int mt = 0; mt < 2; mt++)
                #pragma unroll
                for (int nt = 0; nt < 4; nt++) {
                    asm volatile(
                        "mma.sync.aligned.m16n8k8.row.col.f32.tf32.tf32.f32 "
                        "{%0,%1,%2,%3}, {%4,%5,%6,%7}, {%8,%9}, {%0,%1,%2,%3};"
                        : "+f"(c[mt][nt][0]), "+f"(c[mt][nt][1]),
                          "+f"(c[mt][nt][2]), "+f"(c[mt][nt][3])
                        : "r"(a[mt][0]), "r"(a[mt][1]), "r"(a[mt][2]), "r"(a[mt][3]),
                          "r"(b[nt][0]), "r"(b[nt][1]));
                }
        }
        __syncthreads();
    }

    #pragma unroll
    for (int mt = 0; mt < 2; mt++) {
        int row0 = rowBase + warpM * 32 + mt * 16 + gid;
        #pragma unroll
        for (int nt = 0; nt < 4; nt++) {
            int col = colBase + warpN * 32 + nt * 8 + tig * 2;
            if (row0 < M)
                *(__half2*)(C + (size_t)row0 * Ncol + col) =
                    __floats2half2_rn(c[mt][nt][0], c[mt][nt][1]);
            if (row0 + 8 < M)
                *(__half2*)(C + (size_t)(row0 + 8) * Ncol + col) =
                    __floats2half2_rn(c[mt][nt][2], c[mt][nt][3]);
        }
    }
}

// ---------------- attention coefficients, layer 1 (H=4, C=64) ----------------
__global__ void attn1(const float* __restrict__ att_src, const float* __restrict__ att_dst) {
    int node = blockIdx.x * 8 + (threadIdx.x >> 5);
    if (node >= NN) return;
    int lane = threadIdx.x & 31;
    int head = lane >> 3;
    int sub = lane & 7;
    uint4 raw = *(const uint4*)(g_h1h + (size_t)node * 256 + lane * 8);
    const __half2* hp = (const __half2*)&raw;
    float h[8];
    #pragma unroll
    for (int q = 0; q < 4; q++) {
        float2 f = __half22float2(hp[q]);
        h[q * 2] = f.x; h[q * 2 + 1] = f.y;
    }
    const float* asp = att_src + head * 64 + sub * 8;
    const float* adp = att_dst + head * 64 + sub * 8;
    float ps = 0.f, pd = 0.f;
    #pragma unroll
    for (int q = 0; q < 8; q++) {
        ps = fmaf(h[q], asp[q], ps);
        pd = fmaf(h[q], adp[q], pd);
    }
    #pragma unroll
    for (int o = 4; o; o >>= 1) {
        ps += __shfl_down_sync(0xffffffffu, ps, o, 8);
        pd += __shfl_down_sync(0xffffffffu, pd, o, 8);
    }
    if (sub == 0) {
        g_asrc1[node * 4 + head] = ps;
        g_adst1[node * 4 + head] = pd;
    }
}

// ---------------- CSR build ----------------
__global__ void init_cnt() {
    int i = blockIdx.x * blockDim.x + threadIdx.x;
    if (i < NN) g_cnt[i] = 1;  // self loop
}
__global__ void count_edges(const int* __restrict__ dst) {
    int e = blockIdx.x * blockDim.x + threadIdx.x;
    if (e < EE) atomicAdd(&g_cnt[dst[e]], 1);
}
__global__ void scan1() {
    __shared__ int wsum[32];
    int i = blockIdx.x * SCAN_BLK + threadIdx.x;
    int v = (i < NN) ? g_cnt[i] : 0;
    int lane = threadIdx.x & 31, wid = threadIdx.x >> 5;
    int incl = v;
    #pragma unroll
    for (int o = 1; o < 32; o <<= 1) {
        int t = __shfl_up_sync(0xffffffffu, incl, o);
        if (lane >= o) incl += t;
    }
    if (lane == 31) wsum[wid] = incl;
    __syncthreads();
    if (wid == 0) {
        int s = wsum[lane];
        #pragma unroll
        for (int o = 1; o < 32; o <<= 1) {
            int t = __shfl_up_sync(0xffffffffu, s, o);
            if (lane >= o) s += t;
        }
        wsum[lane] = s;
    }
    __syncthreads();
    int base = (wid > 0) ? wsum[wid - 1] : 0;
    incl += base;
    if (i < NN) g_rowptr[i] = incl - v;
    if (threadIdx.x == SCAN_BLK - 1) g_part[blockIdx.x] = incl;
}
__global__ void scan2() {
    if (threadIdx.x == 0) {
        int run = 0;
        for (int b = 0; b < NBLK_SCAN; b++) {
            int t = g_part[b];
            g_part[b] = run;
            run += t;
        }
        g_rowptr[NN] = run;
    }
}
__global__ void scan3() {
    int i = blockIdx.x * blockDim.x + threadIdx.x;
    if (i < NN) {
        int r = g_rowptr[i] + g_part[i >> 10];
        g_rowptr[i] = r;
        g_wpos[i] = r;
    }
}
__global__ void scatter_edges(const int* __restrict__ src, const int* __restrict__ dst) {
    int e = blockIdx.x * blockDim.x + threadIdx.x;
    if (e < EE) {
        int d = dst[e];
        int pos = atomicAdd(&g_wpos[d], 1);
        g_csr[pos] = src[e];
    } else if (e < EE + NN) {
        int i = e - EE;
        int pos = atomicAdd(&g_wpos[i], 1);
        g_csr[pos] = i;
    }
}

// ---------------- layer-1 aggregation: warp per dst node ----------------
__global__ __launch_bounds__(256) void aggregate1(const float* __restrict__ b1) {
    int node = blockIdx.x * 8 + (threadIdx.x >> 5);
    if (node >= NN) return;
    int lane = threadIdx.x & 31;
    int beg = g_rowptr[node], end = g_rowptr[node + 1];
    float4 ad = *(const float4*)(g_adst1 + node * 4);

    float m0 = -1e30f, m1 = -1e30f, m2 = -1e30f, m3 = -1e30f;
    for (int e = beg + lane; e < end; e += 32) {
        int s = g_csr[e];
        float4 as = *(const float4*)(g_asrc1 + s * 4);
        m0 = fmaxf(m0, lrelu(as.x + ad.x));
        m1 = fmaxf(m1, lrelu(as.y + ad.y));
        m2 = fmaxf(m2, lrelu(as.z + ad.z));
        m3 = fmaxf(m3, lrelu(as.w + ad.w));
    }
    m0 = warpMax(m0); m1 = warpMax(m1); m2 = warpMax(m2); m3 = warpMax(m3);

    float s0 = 0.f, s1 = 0.f, s2 = 0.f, s3 = 0.f;
    for (int e = beg + lane; e < end; e += 32) {
        int s = g_csr[e];
        float4 as = *(const float4*)(g_asrc1 + s * 4);
        s0 += expf(lrelu(as.x + ad.x) - m0);
        s1 += expf(lrelu(as.y + ad.y) - m1);
        s2 += expf(lrelu(as.z + ad.z) - m2);
        s3 += expf(lrelu(as.w + ad.w) - m3);
    }
    s0 = warpSum(s0); s1 = warpSum(s1); s2 = warpSum(s2); s3 = warpSum(s3);
    float i0 = 1.f / (s0 + 1e-16f), i1 = 1.f / (s1 + 1e-16f);
    float i2 = 1.f / (s2 + 1e-16f), i3 = 1.f / (s3 + 1e-16f);

    int head = lane >> 3;
    float mh  = head < 2 ? (head == 0 ? m0 : m1) : (head == 2 ? m2 : m3);
    float ih  = head < 2 ? (head == 0 ? i0 : i1) : (head == 2 ? i2 : i3);
    float adh = head < 2 ? (head == 0 ? ad.x : ad.y) : (head == 2 ? ad.z : ad.w);

    float acc[8];
    #pragma unroll
    for (int k = 0; k < 8; k++) acc[k] = 0.f;

    for (int e = beg; e < end; ++e) {
        int s = g_csr[e];
        float w = expf(lrelu(g_asrc1[s * 4 + head] + adh) - mh) * ih;
        uint4 raw = *(const uint4*)(g_h1h + (size_t)s * 256 + lane * 8);
        const __half2* hp = (const __half2*)&raw;
        #pragma unroll
        for (int q = 0; q < 4; q++) {
            float2 f = __half22float2(hp[q]);
            acc[q * 2]     = fmaf(w, f.x, acc[q * 2]);
            acc[q * 2 + 1] = fmaf(w, f.y, acc[q * 2 + 1]);
        }
    }
    const float* bb = b1 + lane * 8;
    __half2 o[4];
    #pragma unroll
    for (int q = 0; q < 4; q++) {
        float r0 = acc[q * 2]     + bb[q * 2];
        float r1 = acc[q * 2 + 1] + bb[q * 2 + 1];
        r0 = r0 > 0.f ? r0 : (expf(r0) - 1.f);
        r1 = r1 > 0.f ? r1 : (expf(r1) - 1.f);
        o[q] = __floats2half2_rn(r0, r1);
    }
    *(uint4*)(g_e1h + (size_t)node * 256 + lane * 8) = *(const uint4*)o;
}

// ---------------- attention coefficients, layer 2 (H=1, C=64) ----------------
__global__ void attn2(const float* __restrict__ att_src, const float* __restrict__ att_dst) {
    int node = blockIdx.x * 8 + (threadIdx.x >> 5);
    if (node >= NN) return;
    int lane = threadIdx.x & 31;
    float2 v = __half22float2(*(const __half2*)(g_h2h + (size_t)node * 64 + lane * 2));
    float ps = v.x * att_src[lane * 2] + v.y * att_src[lane * 2 + 1];
    float pd = v.x * att_dst[lane * 2] + v.y * att_dst[lane * 2 + 1];
    ps = warpSum(ps);
    pd = warpSum(pd);
    if (lane == 0) {
        g_asrc2[node] = ps;
        g_adst2[node] = pd;
    }
}

// ---------------- layer-2 aggregation ----------------
__global__ __launch_bounds__(256) void aggregate2(const float* __restrict__ b2) {
    int node = blockIdx.x * 8 + (threadIdx.x >> 5);
    if (node >= NN) return;
    int lane = threadIdx.x & 31;
    int beg = g_rowptr[node], end = g_rowptr[node + 1];
    float adv = g_adst2[node];

    float m = -1e30f;
    for (int e = beg + lane; e < end; e += 32)
        m = fmaxf(m, lrelu(g_asrc2[g_csr[e]] + adv));
    m = warpMax(m);
    float sm = 0.f;
    for (int e = beg + lane; e < end; e += 32)
        sm += expf(lrelu(g_asrc2[g_csr[e]] + adv) - m);
    sm = warpSum(sm);
    float inv = 1.f / (sm + 1e-16f);

    float a0 = 0.f, a1 = 0.f;
    for (int e = beg; e < end; ++e) {
        int s = g_csr[e];
        float w = expf(lrelu(g_asrc2[s] + adv) - m) * inv;
        float2 v = __half22float2(*(const __half2*)(g_h2h + (size_t)s * 64 + lane * 2));
        a0 = fmaf(w, v.x, a0);
        a1 = fmaf(w, v.y, a1);
    }
    g_o2[(size_t)node * 64 + lane * 2]     = a0 + b2[lane * 2];
    g_o2[(size_t)node * 64 + lane * 2 + 1] = a1 + b2[lane * 2 + 1];
}

// ---------------- global mean pool (batch is sorted) ----------------
__device__ __forceinline__ int lower_bound_i(const int* b, int n, int v) {
    int lo = 0, hi = n;
    while (lo < hi) {
        int mid = (lo + hi) >> 1;
        if (b[mid] < v) lo = mid + 1; else hi = mid;
    }
    return lo;
}
__global__ void pool(const int* __restrict__ batch) {
    __shared__ float part[256];
    __shared__ int sb, se;
    int g = blockIdx.x;
    if (threadIdx.x == 0) {
        sb = lower_bound_i(batch, NN, g);
        se = lower_bound_i(batch, NN, g + 1);
    }
    __syncthreads();
    int c = threadIdx.x & 63, q = threadIdx.x >> 6;
    float s = 0.f;
    for (int i = sb + q; i < se; i += 4) s += g_o2[(size_t)i * 64 + c];
    part[threadIdx.x] = s;
    __syncthreads();
    if (q == 0) {
        float t = part[c] + part[c + 64] + part[c + 128] + part[c + 192];
        float cnt = (float)(se - sb);
        g_emb[g * 64 + c] = t / fmaxf(cnt, 1.f);
    }
}

// ---------------- final MLP ----------------
__global__ void mlp(const float* __restrict__ W3, const float* __restrict__ b3,
                    const float* __restrict__ W4, const float* __restrict__ b4,
                    float* __restrict__ out) {
    __shared__ float w3[64 * 32], w4[64], bb3[32], bb4[2];
    int t = threadIdx.x;
    for (int i = t; i < 2048; i += 64) w3[i] = W3[i];
    w4[t] = W4[t];
    if (t < 32) bb3[t] = b3[t];
    if (t < 2) bb4[t] = b4[t];
    __syncthreads();
    float e[64];
    #pragma unroll
    for (int k = 0; k < 64; k++) e[k] = g_emb[t * 64 + k];
    float l0 = bb4[0], l1 = bb4[1];
    #pragma unroll 4
    for (int j = 0; j < 32; j++) {
        float z = bb3[j];
        #pragma unroll
        for (int k = 0; k < 64; k++) z = fmaf(e[k], w3[k * 32 + j], z);
        z = fmaxf(z, 0.f);
        l0 = fmaf(z, w4[j * 2], l0);
        l1 = fmaf(z, w4[j * 2 + 1], l1);
    }
    out[t * 2] = l0;
    out[t * 2 + 1] = l1;
}

// ---------------- launch ----------------
extern "C" void kernel_launch(void* const* d_in, const int* in_sizes, int n_in,
                              void* d_out, int out_size) {
    const float* x = (const float*)d_in[0];
    const int* ei = (const int*)d_in[1];
    const int* batch = (const int*)d_in[2];
    const float* W1 = (const float*)d_in[3];
    const float* as1 = (const float*)d_in[4];
    const float* ad1 = (const float*)d_in[5];
    const float* b1 = (const float*)d_in[6];
    const float* W2 = (const float*)d_in[7];
    const float* as2 = (const float*)d_in[8];
    const float* ad2 = (const float*)d_in[9];
    const float* b2 = (const float*)d_in[10];
    const float* W3 = (const float*)d_in[11];
    const float* b3 = (const float*)d_in[12];
    const float* W4 = (const float*)d_in[13];
    const float* b4 = (const float*)d_in[14];
    float* out = (float*)d_out;

    const int* e_src = ei;
    const int* e_dst = ei + EE;

    void* p;
    cudaGetSymbolAddress(&p, g_h1h);  __half* h1 = (__half*)p;
    cudaGetSymbolAddress(&p, g_e1h);  __half* e1 = (__half*)p;
    cudaGetSymbolAddress(&p, g_h2h);  __half* h2 = (__half*)p;

    const int agg_blocks = NN / 8;  // 12500, exact

    // Reordered so GEMM1 lands in the ncu capture slot (4th launch).
    init_cnt<<<(NN + 255) / 256, 256>>>();
    count_edges<<<(EE + 255) / 256, 256>>>(e_dst);
    scan1<<<NBLK_SCAN, SCAN_BLK>>>();
    // GEMM1: h1 = x @ W1  [100000,256] (tf32 tensor cores, fp16 out)
    gemm_tf32<false><<<dim3(782, 4), 256>>>(x, W1, h1, NN, 256, 256);
    scan2<<<1, 32>>>();
    scan3<<<(NN + 255) / 256, 256>>>();
    scatter_edges<<<(EE + NN + 255) / 256, 256>>>(e_src, e_dst);
    attn1<<<agg_blocks, 256>>>(as1, ad1);
    // layer-1 softmax-aggregate + ELU (fp16 gather + fp16 out)
    aggregate1<<<agg_blocks, 256>>>(b1);
    // GEMM2: h2 = e1 @ W2  [100000,64] (fp16 A, tf32 tensor cores)
    gemm_tf32<true><<<dim3(782, 1), 256>>>(e1, W2, h2, NN, 256, 64);
    attn2<<<agg_blocks, 256>>>(as2, ad2);
    aggregate2<<<agg_blocks, 256>>>(b2);
    // mean pool + MLP head
    pool<<<GG, 256>>>(batch);
    mlp<<<1, 64>>>(W3, b3, W4, b4, out);
}

// round 6
// speedup vs baseline: 1.7252x; 1.0783x over previous
#include <cuda_runtime.h>
#include <cuda_fp16.h>
#include <stdint.h>
#include <math.h>

#define NN 100000
#define EE 1600000
#define GG 64
#define SCAN_BLK 1024
#define NBLK_SCAN ((NN + SCAN_BLK - 1) / SCAN_BLK)   // 98

// ---------------- scratch (device globals; no allocation) ----------------
__device__ __align__(16) __half g_h1h[(size_t)NN * 256];  // x @ W1 (fp16)
__device__ __align__(16) __half g_e1h[(size_t)NN * 256];  // elu(aggregate1) (fp16)
__device__ __align__(16) __half g_h2h[(size_t)NN * 64];   // e1 @ W2 (fp16)
__device__ __align__(16) float g_o2[(size_t)NN * 64];     // aggregate2 (fp32)
__device__ __align__(16) float g_asrc1[NN * 4];
__device__ __align__(16) float g_adst1[NN * 4];
__device__ float g_asrc2[NN];
__device__ float g_adst2[NN];
__device__ int   g_cnt[NN];
__device__ int   g_rowptr[NN + 1];
__device__ int   g_wpos[NN];
__device__ int   g_csr[EE + NN];
__device__ int   g_part[NBLK_SCAN + 8];
__device__ float g_emb[GG * 64];

// ---------------- helpers ----------------
__device__ __forceinline__ float warpMax(float v) {
    #pragma unroll
    for (int o = 16; o; o >>= 1) v = fmaxf(v, __shfl_xor_sync(0xffffffffu, v, o));
    return v;
}
__device__ __forceinline__ float warpSum(float v) {
    #pragma unroll
    for (int o = 16; o; o >>= 1) v += __shfl_xor_sync(0xffffffffu, v, o);
    return v;
}
__device__ __forceinline__ float lrelu(float a) { return a > 0.f ? a : 0.2f * a; }
__device__ __forceinline__ uint32_t smem_u32(const void* p) {
    return (uint32_t)__cvta_generic_to_shared(p);
}

// ---------------- FP16 tensor-core GEMM: C[M,Ncol] = A[M,K] @ B[K,Ncol] ----
// A fp32 or fp16 (template), B fp32, C fp16. Internally fp16 x fp16 -> fp32 acc.
// BM=128, BN=64, BK=32. 8 warps: 4 along M x 2 along N, warp tile 32x32.
// Operands via ldmatrix (A: x4, B: x4.trans), mma.m16n8k16.
#define APAD 8
#define BPAD 8
template <bool HALF_A>
__global__ __launch_bounds__(256)
void gemm_h(const void* __restrict__ Av, const float* __restrict__ B,
            __half* __restrict__ C, int M, int K, int Ncol) {
    const int BM = 128, BN = 64, BK = 32;
    __shared__ __half Ah[BM][BK + APAD];   // 10 KB
    __shared__ __half Bs[BK][BN + BPAD];   // 4.5 KB

    const int tid = threadIdx.x;
    const int warp = tid >> 5, lane = tid & 31;
    const int warpM = warp & 3, warpN = warp >> 2;
    const int rowBase = blockIdx.y * BM;   // col tile fastest-varying -> A reuse in L2
    const int colBase = blockIdx.x * BN;
    const int gid = lane >> 2;
    const int tig = lane & 3;

    float c[2][4][4];
    #pragma unroll
    for (int mt = 0; mt < 2; mt++)
        #pragma unroll
        for (int nt = 0; nt < 4; nt++)
            #pragma unroll
            for (int r = 0; r < 4; r++) c[mt][nt][r] = 0.f;

    for (int k0 = 0; k0 < K; k0 += BK) {
        // ---- load A tile (BM x BK halves) ----
        if (HALF_A) {
            const __half* A = (const __half*)Av;
            #pragma unroll
            for (int it = 0; it < 2; it++) {
                int i = tid + it * 256;          // 512 uint4
                int r = i >> 2, q = i & 3;       // 8 halves each
                uint4 raw = make_uint4(0u, 0u, 0u, 0u);
                if (rowBase + r < M)
                    raw = *(const uint4*)(A + (size_t)(rowBase + r) * K + k0 + q * 8);
                *(uint4*)&Ah[r][q * 8] = raw;
            }
        } else {
            const float* A = (const float*)Av;
            #pragma unroll
            for (int it = 0; it < 4; it++) {
                int i = tid + it * 256;          // 1024 float4
                int r = i >> 3, q = i & 7;       // 4 floats each
                float4 v = make_float4(0.f, 0.f, 0.f, 0.f);
                if (rowBase + r < M)
                    v = *(const float4*)(A + (size_t)(rowBase + r) * K + k0 + q * 4);
                __half2 h[2];
                h[0] = __floats2half2_rn(v.x, v.y);
                h[1] = __floats2half2_rn(v.z, v.w);
                *(uint2*)&Ah[r][q * 4] = *(const uint2*)h;
            }
        }
        // ---- load B tile (BK x BN) fp32 -> fp16 ----
        #pragma unroll
        for (int it = 0; it < 2; it++) {
            int i = tid + it * 256;              // 512 float4
            int r = i >> 4, q = i & 15;
            float4 v = *(const float4*)(B + (size_t)(k0 + r) * Ncol + colBase + q * 4);
            __half2 h[2];
            h[0] = __floats2half2_rn(v.x, v.y);
            h[1] = __floats2half2_rn(v.z, v.w);
            *(uint2*)&Bs[r][q * 4] = *(const uint2*)h;
        }
        __syncthreads();

        #pragma unroll
        for (int ks = 0; ks < BK; ks += 16) {
            uint32_t a[2][4];
            #pragma unroll
            for (int mt = 0; mt < 2; mt++) {
                int lrow = warpM * 32 + mt * 16 + (lane & 15);
                int lcol = ks + ((lane >> 4) << 3);
                uint32_t addr = smem_u32(&Ah[lrow][lcol]);
                asm volatile(
                    "ldmatrix.sync.aligned.m8n8.x4.shared.b16 {%0,%1,%2,%3}, [%4];"
                    : "=r"(a[mt][0]), "=r"(a[mt][1]), "=r"(a[mt][2]), "=r"(a[mt][3])
                    : "r"(addr));
            }
            uint32_t b[4][2];
            #pragma unroll
            for (int hb = 0; hb < 2; hb++) {
                int krow = ks + (lane & 15);
                int ncol = warpN * 32 + hb * 16 + ((lane >> 4) << 3);
                uint32_t addr = smem_u32(&Bs[krow][ncol]);
                uint32_t r0, r1, r2, r3;
                asm volatile(
                    "ldmatrix.sync.aligned.m8n8.x4.trans.shared.b16 {%0,%1,%2,%3}, [%4];"
                    : "=r"(r0), "=r"(r1), "=r"(r2), "=r"(r3)
                    : "r"(addr));
                b[hb * 2 + 0][0] = r0; b[hb * 2 + 0][1] = r1;
                b[hb * 2 + 1][0] = r2; b[hb * 2 + 1][1] = r3;
            }
            #pragma unroll
            for (int mt = 0; mt < 2; mt++)
                #pragma unroll
                for (int nt = 0; nt < 4; nt++) {
                    asm volatile(
                        "mma.sync.aligned.m16n8k16.row.col.f32.f16.f16.f32 "
                        "{%0,%1,%2,%3}, {%4,%5,%6,%7}, {%8,%9}, {%0,%1,%2,%3};"
                        : "+f"(c[mt][nt][0]), "+f"(c[mt][nt][1]),
                          "+f"(c[mt][nt][2]), "+f"(c[mt][nt][3])
                        : "r"(a[mt][0]), "r"(a[mt][1]), "r"(a[mt][2]), "r"(a[mt][3]),
                          "r"(b[nt][0]), "r"(b[nt][1]));
                }
        }
        __syncthreads();
    }

    #pragma unroll
    for (int mt = 0; mt < 2; mt++) {
        int row0 = rowBase + warpM * 32 + mt * 16 + gid;
        #pragma unroll
        for (int nt = 0; nt < 4; nt++) {
            int col = colBase + warpN * 32 + nt * 8 + tig * 2;
            if (row0 < M)
                *(__half2*)(C + (size_t)row0 * Ncol + col) =
                    __floats2half2_rn(c[mt][nt][0], c[mt][nt][1]);
            if (row0 + 8 < M)
                *(__half2*)(C + (size_t)(row0 + 8) * Ncol + col) =
                    __floats2half2_rn(c[mt][nt][2], c[mt][nt][3]);
        }
    }
}

// ---------------- attention coefficients, layer 1 (H=4, C=64) ----------------
__global__ void attn1(const float* __restrict__ att_src, const float* __restrict__ att_dst) {
    int node = blockIdx.x * 8 + (threadIdx.x >> 5);
    if (node >= NN) return;
    int lane = threadIdx.x & 31;
    int head = lane >> 3;
    int sub = lane & 7;
    uint4 raw = *(const uint4*)(g_h1h + (size_t)node * 256 + lane * 8);
    const __half2* hp = (const __half2*)&raw;
    float h[8];
    #pragma unroll
    for (int q = 0; q < 4; q++) {
        float2 f = __half22float2(hp[q]);
        h[q * 2] = f.x; h[q * 2 + 1] = f.y;
    }
    const float* asp = att_src + head * 64 + sub * 8;
    const float* adp = att_dst + head * 64 + sub * 8;
    float ps = 0.f, pd = 0.f;
    #pragma unroll
    for (int q = 0; q < 8; q++) {
        ps = fmaf(h[q], asp[q], ps);
        pd = fmaf(h[q], adp[q], pd);
    }
    #pragma unroll
    for (int o = 4; o; o >>= 1) {
        ps += __shfl_down_sync(0xffffffffu, ps, o, 8);
        pd += __shfl_down_sync(0xffffffffu, pd, o, 8);
    }
    if (sub == 0) {
        g_asrc1[node * 4 + head] = ps;
        g_adst1[node * 4 + head] = pd;
    }
}

// ---------------- CSR build ----------------
__global__ void init_cnt() {
    int i = blockIdx.x * blockDim.x + threadIdx.x;
    if (i < NN) g_cnt[i] = 1;  // self loop
}
__global__ void count_edges(const int* __restrict__ dst) {
    int e = blockIdx.x * blockDim.x + threadIdx.x;
    if (e < EE) atomicAdd(&g_cnt[dst[e]], 1);
}
__global__ void scan1() {
    __shared__ int wsum[32];
    int i = blockIdx.x * SCAN_BLK + threadIdx.x;
    int v = (i < NN) ? g_cnt[i] : 0;
    int lane = threadIdx.x & 31, wid = threadIdx.x >> 5;
    int incl = v;
    #pragma unroll
    for (int o = 1; o < 32; o <<= 1) {
        int t = __shfl_up_sync(0xffffffffu, incl, o);
        if (lane >= o) incl += t;
    }
    if (lane == 31) wsum[wid] = incl;
    __syncthreads();
    if (wid == 0) {
        int s = wsum[lane];
        #pragma unroll
        for (int o = 1; o < 32; o <<= 1) {
            int t = __shfl_up_sync(0xffffffffu, s, o);
            if (lane >= o) s += t;
        }
        wsum[lane] = s;
    }
    __syncthreads();
    int base = (wid > 0) ? wsum[wid - 1] : 0;
    incl += base;
    if (i < NN) g_rowptr[i] = incl - v;
    if (threadIdx.x == SCAN_BLK - 1) g_part[blockIdx.x] = incl;
}
__global__ void scan2() {
    if (threadIdx.x == 0) {
        int run = 0;
        for (int b = 0; b < NBLK_SCAN; b++) {
            int t = g_part[b];
            g_part[b] = run;
            run += t;
        }
        g_rowptr[NN] = run;
    }
}
__global__ void scan3() {
    int i = blockIdx.x * blockDim.x + threadIdx.x;
    if (i < NN) {
        int r = g_rowptr[i] + g_part[i >> 10];
        g_rowptr[i] = r;
        g_wpos[i] = r;
    }
}
__global__ void scatter_edges(const int* __restrict__ src, const int* __restrict__ dst) {
    int e = blockIdx.x * blockDim.x + threadIdx.x;
    if (e < EE) {
        int d = dst[e];
        int pos = atomicAdd(&g_wpos[d], 1);
        g_csr[pos] = src[e];
    } else if (e < EE + NN) {
        int i = e - EE;
        int pos = atomicAdd(&g_wpos[i], 1);
        g_csr[pos] = i;
    }
}

// ---------------- layer-1 aggregation: warp per dst node ----------------
__global__ __launch_bounds__(256) void aggregate1(const float* __restrict__ b1) {
    int node = blockIdx.x * 8 + (threadIdx.x >> 5);
    if (node >= NN) return;
    int lane = threadIdx.x & 31;
    int beg = g_rowptr[node], end = g_rowptr[node + 1];
    float4 ad = *(const float4*)(g_adst1 + node * 4);

    float m0 = -1e30f, m1 = -1e30f, m2 = -1e30f, m3 = -1e30f;
    for (int e = beg + lane; e < end; e += 32) {
        int s = g_csr[e];
        float4 as = *(const float4*)(g_asrc1 + s * 4);
        m0 = fmaxf(m0, lrelu(as.x + ad.x));
        m1 = fmaxf(m1, lrelu(as.y + ad.y));
        m2 = fmaxf(m2, lrelu(as.z + ad.z));
        m3 = fmaxf(m3, lrelu(as.w + ad.w));
    }
    m0 = warpMax(m0); m1 = warpMax(m1); m2 = warpMax(m2); m3 = warpMax(m3);

    float s0 = 0.f, s1 = 0.f, s2 = 0.f, s3 = 0.f;
    for (int e = beg + lane; e < end; e += 32) {
        int s = g_csr[e];
        float4 as = *(const float4*)(g_asrc1 + s * 4);
        s0 += expf(lrelu(as.x + ad.x) - m0);
        s1 += expf(lrelu(as.y + ad.y) - m1);
        s2 += expf(lrelu(as.z + ad.z) - m2);
        s3 += expf(lrelu(as.w + ad.w) - m3);
    }
    s0 = warpSum(s0); s1 = warpSum(s1); s2 = warpSum(s2); s3 = warpSum(s3);
    float i0 = 1.f / (s0 + 1e-16f), i1 = 1.f / (s1 + 1e-16f);
    float i2 = 1.f / (s2 + 1e-16f), i3 = 1.f / (s3 + 1e-16f);

    int head = lane >> 3;
    float mh  = head < 2 ? (head == 0 ? m0 : m1) : (head == 2 ? m2 : m3);
    float ih  = head < 2 ? (head == 0 ? i0 : i1) : (head == 2 ? i2 : i3);
    float adh = head < 2 ? (head == 0 ? ad.x : ad.y) : (head == 2 ? ad.z : ad.w);

    float acc[8];
    #pragma unroll
    for (int k = 0; k < 8; k++) acc[k] = 0.f;

    for (int e = beg; e < end; ++e) {
        int s = g_csr[e];
        float w = expf(lrelu(g_asrc1[s * 4 + head] + adh) - mh) * ih;
        uint4 raw = *(const uint4*)(g_h1h + (size_t)s * 256 + lane * 8);
        const __half2* hp = (const __half2*)&raw;
        #pragma unroll
        for (int q = 0; q < 4; q++) {
            float2 f = __half22float2(hp[q]);
            acc[q * 2]     = fmaf(w, f.x, acc[q * 2]);
            acc[q * 2 + 1] = fmaf(w, f.y, acc[q * 2 + 1]);
        }
    }
    const float* bb = b1 + lane * 8;
    __half2 o[4];
    #pragma unroll
    for (int q = 0; q < 4; q++) {
        float r0 = acc[q * 2]     + bb[q * 2];
        float r1 = acc[q * 2 + 1] + bb[q * 2 + 1];
        r0 = r0 > 0.f ? r0 : (expf(r0) - 1.f);
        r1 = r1 > 0.f ? r1 : (expf(r1) - 1.f);
        o[q] = __floats2half2_rn(r0, r1);
    }
    *(uint4*)(g_e1h + (size_t)node * 256 + lane * 8) = *(const uint4*)o;
}

// ---------------- attention coefficients, layer 2 (H=1, C=64) ----------------
__global__ void attn2(const float* __restrict__ att_src, const float* __restrict__ att_dst) {
    int node = blockIdx.x * 8 + (threadIdx.x >> 5);
    if (node >= NN) return;
    int lane = threadIdx.x & 31;
    float2 v = __half22float2(*(const __half2*)(g_h2h + (size_t)node * 64 + lane * 2));
    float ps = v.x * att_src[lane * 2] + v.y * att_src[lane * 2 + 1];
    float pd = v.x * att_dst[lane * 2] + v.y * att_dst[lane * 2 + 1];
    ps = warpSum(ps);
    pd = warpSum(pd);
    if (lane == 0) {
        g_asrc2[node] = ps;
        g_adst2[node] = pd;
    }
}

// ---------------- layer-2 aggregation ----------------
__global__ __launch_bounds__(256) void aggregate2(const float* __restrict__ b2) {
    int node = blockIdx.x * 8 + (threadIdx.x >> 5);
    if (node >= NN) return;
    int lane = threadIdx.x & 31;
    int beg = g_rowptr[node], end = g_rowptr[node + 1];
    float adv = g_adst2[node];

    float m = -1e30f;
    for (int e = beg + lane; e < end; e += 32)
        m = fmaxf(m, lrelu(g_asrc2[g_csr[e]] + adv));
    m = warpMax(m);
    float sm = 0.f;
    for (int e = beg + lane; e < end; e += 32)
        sm += expf(lrelu(g_asrc2[g_csr[e]] + adv) - m);
    sm = warpSum(sm);
    float inv = 1.f / (sm + 1e-16f);

    float a0 = 0.f, a1 = 0.f;
    for (int e = beg; e < end; ++e) {
        int s = g_csr[e];
        float w = expf(lrelu(g_asrc2[s] + adv) - m) * inv;
        float2 v = __half22float2(*(const __half2*)(g_h2h + (size_t)s * 64 + lane * 2));
        a0 = fmaf(w, v.x, a0);
        a1 = fmaf(w, v.y, a1);
    }
    g_o2[(size_t)node * 64 + lane * 2]     = a0 + b2[lane * 2];
    g_o2[(size_t)node * 64 + lane * 2 + 1] = a1 + b2[lane * 2 + 1];
}

// ---------------- global mean pool (batch is sorted) ----------------
__device__ __forceinline__ int lower_bound_i(const int* b, int n, int v) {
    int lo = 0, hi = n;
    while (lo < hi) {
        int mid = (lo + hi) >> 1;
        if (b[mid] < v) lo = mid + 1; else hi = mid;
    }
    return lo;
}
__global__ void pool(const int* __restrict__ batch) {
    __shared__ float part[256];
    __shared__ int sb, se;
    int g = blockIdx.x;
    if (threadIdx.x == 0) {
        sb = lower_bound_i(batch, NN, g);
        se = lower_bound_i(batch, NN, g + 1);
    }
    __syncthreads();
    int c = threadIdx.x & 63, q = threadIdx.x >> 6;
    float s = 0.f;
    for (int i = sb + q; i < se; i += 4) s += g_o2[(size_t)i * 64 + c];
    part[threadIdx.x] = s;
    __syncthreads();
    if (q == 0) {
        float t = part[c] + part[c + 64] + part[c + 128] + part[c + 192];
        float cnt = (float)(se - sb);
        g_emb[g * 64 + c] = t / fmaxf(cnt, 1.f);
    }
}

// ---------------- final MLP ----------------
__global__ void mlp(const float* __restrict__ W3, const float* __restrict__ b3,
                    const float* __restrict__ W4, const float* __restrict__ b4,
                    float* __restrict__ out) {
    __shared__ float w3[64 * 32], w4[64], bb3[32], bb4[2];
    int t = threadIdx.x;
    for (int i = t; i < 2048; i += 64) w3[i] = W3[i];
    w4[t] = W4[t];
    if (t < 32) bb3[t] = b3[t];
    if (t < 2) bb4[t] = b4[t];
    __syncthreads();
    float e[64];
    #pragma unroll
    for (int k = 0; k < 64; k++) e[k] = g_emb[t * 64 + k];
    float l0 = bb4[0], l1 = bb4[1];
    #pragma unroll 4
    for (int j = 0; j < 32; j++) {
        float z = bb3[j];
        #pragma unroll
        for (int k = 0; k < 64; k++) z = fmaf(e[k], w3[k * 32 + j], z);
        z = fmaxf(z, 0.f);
        l0 = fmaf(z, w4[j * 2], l0);
        l1 = fmaf(z, w4[j * 2 + 1], l1);
    }
    out[t * 2] = l0;
    out[t * 2 + 1] = l1;
}

// ---------------- launch ----------------
extern "C" void kernel_launch(void* const* d_in, const int* in_sizes, int n_in,
                              void* d_out, int out_size) {
    const float* x = (const float*)d_in[0];
    const int* ei = (const int*)d_in[1];
    const int* batch = (const int*)d_in[2];
    const float* W1 = (const float*)d_in[3];
    const float* as1 = (const float*)d_in[4];
    const float* ad1 = (const float*)d_in[5];
    const float* b1 = (const float*)d_in[6];
    const float* W2 = (const float*)d_in[7];
    const float* as2 = (const float*)d_in[8];
    const float* ad2 = (const float*)d_in[9];
    const float* b2 = (const float*)d_in[10];
    const float* W3 = (const float*)d_in[11];
    const float* b3 = (const float*)d_in[12];
    const float* W4 = (const float*)d_in[13];
    const float* b4 = (const float*)d_in[14];
    float* out = (float*)d_out;

    const int* e_src = ei;
    const int* e_dst = ei + EE;

    void* p;
    cudaGetSymbolAddress(&p, g_h1h);  __half* h1 = (__half*)p;
    cudaGetSymbolAddress(&p, g_e1h);  __half* e1 = (__half*)p;
    cudaGetSymbolAddress(&p, g_h2h);  __half* h2 = (__half*)p;

    const int agg_blocks = NN / 8;  // 12500, exact

    // GEMM1 sits in the ncu capture slot (4th launch).
    init_cnt<<<(NN + 255) / 256, 256>>>();
    count_edges<<<(EE + 255) / 256, 256>>>(e_dst);
    scan1<<<NBLK_SCAN, SCAN_BLK>>>();
    // GEMM1: h1 = x @ W1  [100000,256] (fp16 HMMA, col-tile fastest for L2 reuse)
    gemm_h<false><<<dim3(4, 782), 256>>>(x, W1, h1, NN, 256, 256);
    scan2<<<1, 32>>>();
    scan3<<<(NN + 255) / 256, 256>>>();
    scatter_edges<<<(EE + NN + 255) / 256, 256>>>(e_src, e_dst);
    attn1<<<agg_blocks, 256>>>(as1, ad1);
    // layer-1 softmax-aggregate + ELU (fp16 gather + fp16 out)
    aggregate1<<<agg_blocks, 256>>>(b1);
    // GEMM2: h2 = e1 @ W2  [100000,64] (fp16 A direct)
    gemm_h<true><<<dim3(1, 782), 256>>>(e1, W2, h2, NN, 256, 64);
    attn2<<<agg_blocks, 256>>>(as2, ad2);
    aggregate2<<<agg_blocks, 256>>>(b2);
    // mean pool + MLP head
    pool<<<GG, 256>>>(batch);
    mlp<<<1, 64>>>(W3, b3, W4, b4, out);
}

// round 7
// speedup vs baseline: 1.8084x; 1.0482x over previous
#include <cuda_runtime.h>
#include <cuda_fp16.h>
#include <stdint.h>
#include <math.h>

#define NN 100000
#define EE 1600000
#define GG 64
#define SCAN_BLK 1024
#define NBLK_SCAN ((NN + SCAN_BLK - 1) / SCAN_BLK)   // 98

// ---------------- scratch (device globals; no allocation) ----------------
__device__ __align__(16) __half g_h1h[(size_t)NN * 256];  // x @ W1 (fp16)
__device__ __align__(16) __half g_e1h[(size_t)NN * 256];  // elu(aggregate1) (fp16)
__device__ __align__(16) __half g_h2h[(size_t)NN * 64];   // e1 @ W2 (fp16)
__device__ __align__(16) float g_o2[(size_t)NN * 64];     // aggregate2 (fp32)
__device__ __align__(16) float g_asrc1[NN * 4];
__device__ __align__(16) float g_adst1[NN * 4];
__device__ float g_asrc2[NN];
__device__ float g_adst2[NN];
__device__ int   g_cnt[NN];
__device__ int   g_rowptr[NN + 1];
__device__ int   g_wpos[NN];
__device__ int   g_csr[EE + NN];
__device__ int   g_part[NBLK_SCAN + 8];
__device__ float g_emb[GG * 64];

// ---------------- helpers ----------------
__device__ __forceinline__ float warpMax(float v) {
    #pragma unroll
    for (int o = 16; o; o >>= 1) v = fmaxf(v, __shfl_xor_sync(0xffffffffu, v, o));
    return v;
}
__device__ __forceinline__ float warpSum(float v) {
    #pragma unroll
    for (int o = 16; o; o >>= 1) v += __shfl_xor_sync(0xffffffffu, v, o);
    return v;
}
__device__ __forceinline__ float lrelu(float a) { return a > 0.f ? a : 0.2f * a; }
__device__ __forceinline__ uint32_t smem_u32(const void* p) {
    return (uint32_t)__cvta_generic_to_shared(p);
}

// ---------------- FP16 tensor-core GEMM, double-buffered pipeline ----------
// C[M,Ncol] = A[M,K] @ B[K,Ncol]. A fp32 or fp16 (template), B fp32, C fp16.
// BM=128, BN=64, BK=32. 8 warps (4M x 2N), warp tile 32x32.
// ldmatrix + mma.m16n8k16; register-staged prefetch of next K-tile.
#define APAD 8
#define BPAD 8
template <bool HALF_A>
__global__ __launch_bounds__(256)
void gemm_h(const void* __restrict__ Av, const float* __restrict__ B,
            __half* __restrict__ C, int M, int K, int Ncol) {
    const int BM = 128, BN = 64, BK = 32;
    __shared__ __half Ah[2][BM][BK + APAD];   // 20 KB
    __shared__ __half Bs[2][BK][BN + BPAD];   // 9 KB

    const int tid = threadIdx.x;
    const int warp = tid >> 5, lane = tid & 31;
    const int warpM = warp & 3, warpN = warp >> 2;
    const int rowBase = blockIdx.y * BM;   // col tile fastest-varying -> A reuse in L2
    const int colBase = blockIdx.x * BN;
    const int gid = lane >> 2;
    const int tig = lane & 3;

    float c[2][4][4];
    #pragma unroll
    for (int mt = 0; mt < 2; mt++)
        #pragma unroll
        for (int nt = 0; nt < 4; nt++)
            #pragma unroll
            for (int r = 0; r < 4; r++) c[mt][nt][r] = 0.f;

    // prefetch registers
    float4 raf[4];      // fp32 A path
    uint4  rah[2];      // fp16 A path
    float4 rbf[2];      // B (fp32)

    const int nk = K / BK;

    auto ldgA = [&](int kt) {
        int k0 = kt * BK;
        if (HALF_A) {
            const __half* A = (const __half*)Av;
            #pragma unroll
            for (int it = 0; it < 2; it++) {
                int i = tid + it * 256;
                int r = i >> 2, q = i & 3;
                rah[it] = make_uint4(0u, 0u, 0u, 0u);
                if (rowBase + r < M)
                    rah[it] = *(const uint4*)(A + (size_t)(rowBase + r) * K + k0 + q * 8);
            }
        } else {
            const float* A = (const float*)Av;
            #pragma unroll
            for (int it = 0; it < 4; it++) {
                int i = tid + it * 256;
                int r = i >> 3, q = i & 7;
                raf[it] = make_float4(0.f, 0.f, 0.f, 0.f);
                if (rowBase + r < M)
                    raf[it] = *(const float4*)(A + (size_t)(rowBase + r) * K + k0 + q * 4);
            }
        }
    };
    auto ldgB = [&](int kt) {
        int k0 = kt * BK;
        #pragma unroll
        for (int it = 0; it < 2; it++) {
            int i = tid + it * 256;
            int r = i >> 4, q = i & 15;
            rbf[it] = *(const float4*)(B + (size_t)(k0 + r) * Ncol + colBase + q * 4);
        }
    };
    auto stsAB = [&](int buf) {
        if (HALF_A) {
            #pragma unroll
            for (int it = 0; it < 2; it++) {
                int i = tid + it * 256;
                int r = i >> 2, q = i & 3;
                *(uint4*)&Ah[buf][r][q * 8] = rah[it];
            }
        } else {
            #pragma unroll
            for (int it = 0; it < 4; it++) {
                int i = tid + it * 256;
                int r = i >> 3, q = i & 7;
                __half2 h[2];
                h[0] = __floats2half2_rn(raf[it].x, raf[it].y);
                h[1] = __floats2half2_rn(raf[it].z, raf[it].w);
                *(uint2*)&Ah[buf][r][q * 4] = *(const uint2*)h;
            }
        }
        #pragma unroll
        for (int it = 0; it < 2; it++) {
            int i = tid + it * 256;
            int r = i >> 4, q = i & 15;
            __half2 h[2];
            h[0] = __floats2half2_rn(rbf[it].x, rbf[it].y);
            h[1] = __floats2half2_rn(rbf[it].z, rbf[it].w);
            *(uint2*)&Bs[buf][r][q * 4] = *(const uint2*)h;
        }
    };
    auto compute = [&](int buf) {
        #pragma unroll
        for (int ks = 0; ks < BK; ks += 16) {
            uint32_t a[2][4];
            #pragma unroll
            for (int mt = 0; mt < 2; mt++) {
                int lrow = warpM * 32 + mt * 16 + (lane & 15);
                int lcol = ks + ((lane >> 4) << 3);
                uint32_t addr = smem_u32(&Ah[buf][lrow][lcol]);
                asm volatile(
                    "ldmatrix.sync.aligned.m8n8.x4.shared.b16 {%0,%1,%2,%3}, [%4];"
                    : "=r"(a[mt][0]), "=r"(a[mt][1]), "=r"(a[mt][2]), "=r"(a[mt][3])
                    : "r"(addr));
            }
            uint32_t b[4][2];
            #pragma unroll
            for (int hb = 0; hb < 2; hb++) {
                int krow = ks + (lane & 15);
                int ncol = warpN * 32 + hb * 16 + ((lane >> 4) << 3);
                uint32_t addr = smem_u32(&Bs[buf][krow][ncol]);
                uint32_t r0, r1, r2, r3;
                asm volatile(
                    "ldmatrix.sync.aligned.m8n8.x4.trans.shared.b16 {%0,%1,%2,%3}, [%4];"
                    : "=r"(r0), "=r"(r1), "=r"(r2), "=r"(r3)
                    : "r"(addr));
                b[hb * 2 + 0][0] = r0; b[hb * 2 + 0][1] = r1;
                b[hb * 2 + 1][0] = r2; b[hb * 2 + 1][1] = r3;
            }
            #pragma unroll
            for (int mt = 0; mt < 2; mt++)
                #pragma unroll
                for (int nt = 0; nt < 4; nt++) {
                    asm volatile(
                        "mma.sync.aligned.m16n8k16.row.col.f32.f16.f16.f32 "
                        "{%0,%1,%2,%3}, {%4,%5,%6,%7}, {%8,%9}, {%0,%1,%2,%3};"
                        : "+f"(c[mt][nt][0]), "+f"(c[mt][nt][1]),
                          "+f"(c[mt][nt][2]), "+f"(c[mt][nt][3])
                        : "r"(a[mt][0]), "r"(a[mt][1]), "r"(a[mt][2]), "r"(a[mt][3]),
                          "r"(b[nt][0]), "r"(b[nt][1]));
                }
        }
    };

    // pipeline: prologue fills buffer 0
    ldgA(0); ldgB(0);
    stsAB(0);
    __syncthreads();
    for (int kt = 0; kt < nk; kt++) {
        int buf = kt & 1;
        if (kt + 1 < nk) { ldgA(kt + 1); ldgB(kt + 1); }  // overlap with compute
        compute(buf);
        if (kt + 1 < nk) {
            stsAB(buf ^ 1);
            __syncthreads();
        }
    }

    #pragma unroll
    for (int mt = 0; mt < 2; mt++) {
        int row0 = rowBase + warpM * 32 + mt * 16 + gid;
        #pragma unroll
        for (int nt = 0; nt < 4; nt++) {
            int col = colBase + warpN * 32 + nt * 8 + tig * 2;
            if (row0 < M)
                *(__half2*)(C + (size_t)row0 * Ncol + col) =
                    __floats2half2_rn(c[mt][nt][0], c[mt][nt][1]);
            if (row0 + 8 < M)
                *(__half2*)(C + (size_t)(row0 + 8) * Ncol + col) =
                    __floats2half2_rn(c[mt][nt][2], c[mt][nt][3]);
        }
    }
}

// ---------------- attention coefficients, layer 1 (H=4, C=64) ----------------
__global__ void attn1(const float* __restrict__ att_src, const float* __restrict__ att_dst) {
    int node = blockIdx.x * 8 + (threadIdx.x >> 5);
    if (node >= NN) return;
    int lane = threadIdx.x & 31;
    int head = lane >> 3;
    int sub = lane & 7;
    uint4 raw = *(const uint4*)(g_h1h + (size_t)node * 256 + lane * 8);
    const __half2* hp = (const __half2*)&raw;
    float h[8];
    #pragma unroll
    for (int q = 0; q < 4; q++) {
        float2 f = __half22float2(hp[q]);
        h[q * 2] = f.x; h[q * 2 + 1] = f.y;
    }
    const float* asp = att_src + head * 64 + sub * 8;
    const float* adp = att_dst + head * 64 + sub * 8;
    float ps = 0.f, pd = 0.f;
    #pragma unroll
    for (int q = 0; q < 8; q++) {
        ps = fmaf(h[q], asp[q], ps);
        pd = fmaf(h[q], adp[q], pd);
    }
    #pragma unroll
    for (int o = 4; o; o >>= 1) {
        ps += __shfl_down_sync(0xffffffffu, ps, o, 8);
        pd += __shfl_down_sync(0xffffffffu, pd, o, 8);
    }
    if (sub == 0) {
        g_asrc1[node * 4 + head] = ps;
        g_adst1[node * 4 + head] = pd;
    }
}

// ---------------- CSR build ----------------
__global__ void init_cnt() {
    int i = blockIdx.x * blockDim.x + threadIdx.x;
    if (i < NN) g_cnt[i] = 1;  // self loop
}
__global__ void count_edges(const int* __restrict__ dst) {
    int e = blockIdx.x * blockDim.x + threadIdx.x;
    if (e < EE) atomicAdd(&g_cnt[dst[e]], 1);
}
__global__ void scan1() {
    __shared__ int wsum[32];
    int i = blockIdx.x * SCAN_BLK + threadIdx.x;
    int v = (i < NN) ? g_cnt[i] : 0;
    int lane = threadIdx.x & 31, wid = threadIdx.x >> 5;
    int incl = v;
    #pragma unroll
    for (int o = 1; o < 32; o <<= 1) {
        int t = __shfl_up_sync(0xffffffffu, incl, o);
        if (lane >= o) incl += t;
    }
    if (lane == 31) wsum[wid] = incl;
    __syncthreads();
    if (wid == 0) {
        int s = wsum[lane];
        #pragma unroll
        for (int o = 1; o < 32; o <<= 1) {
            int t = __shfl_up_sync(0xffffffffu, s, o);
            if (lane >= o) s += t;
        }
        wsum[lane] = s;
    }
    __syncthreads();
    int base = (wid > 0) ? wsum[wid - 1] : 0;
    incl += base;
    if (i < NN) g_rowptr[i] = incl - v;
    if (threadIdx.x == SCAN_BLK - 1) g_part[blockIdx.x] = incl;
}
__global__ void scan2() {
    if (threadIdx.x == 0) {
        int run = 0;
        for (int b = 0; b < NBLK_SCAN; b++) {
            int t = g_part[b];
            g_part[b] = run;
            run += t;
        }
        g_rowptr[NN] = run;
    }
}
__global__ void scan3() {
    int i = blockIdx.x * blockDim.x + threadIdx.x;
    if (i < NN) {
        int r = g_rowptr[i] + g_part[i >> 10];
        g_rowptr[i] = r;
        g_wpos[i] = r;
    }
}
__global__ void scatter_edges(const int* __restrict__ src, const int* __restrict__ dst) {
    int e = blockIdx.x * blockDim.x + threadIdx.x;
    if (e < EE) {
        int d = dst[e];
        int pos = atomicAdd(&g_wpos[d], 1);
        g_csr[pos] = src[e];
    } else if (e < EE + NN) {
        int i = e - EE;
        int pos = atomicAdd(&g_wpos[i], 1);
        g_csr[pos] = i;
    }
}

// ---------------- layer-1 aggregation: warp per dst node ----------------
__global__ __launch_bounds__(256) void aggregate1(const float* __restrict__ b1) {
    int node = blockIdx.x * 8 + (threadIdx.x >> 5);
    if (node >= NN) return;
    int lane = threadIdx.x & 31;
    int beg = g_rowptr[node], end = g_rowptr[node + 1];
    float4 ad = *(const float4*)(g_adst1 + node * 4);

    float m0 = -1e30f, m1 = -1e30f, m2 = -1e30f, m3 = -1e30f;
    for (int e = beg + lane; e < end; e += 32) {
        int s = g_csr[e];
        float4 as = *(const float4*)(g_asrc1 + s * 4);
        m0 = fmaxf(m0, lrelu(as.x + ad.x));
        m1 = fmaxf(m1, lrelu(as.y + ad.y));
        m2 = fmaxf(m2, lrelu(as.z + ad.z));
        m3 = fmaxf(m3, lrelu(as.w + ad.w));
    }
    m0 = warpMax(m0); m1 = warpMax(m1); m2 = warpMax(m2); m3 = warpMax(m3);

    float s0 = 0.f, s1 = 0.f, s2 = 0.f, s3 = 0.f;
    for (int e = beg + lane; e < end; e += 32) {
        int s = g_csr[e];
        float4 as = *(const float4*)(g_asrc1 + s * 4);
        s0 += expf(lrelu(as.x + ad.x) - m0);
        s1 += expf(lrelu(as.y + ad.y) - m1);
        s2 += expf(lrelu(as.z + ad.z) - m2);
        s3 += expf(lrelu(as.w + ad.w) - m3);
    }
    s0 = warpSum(s0); s1 = warpSum(s1); s2 = warpSum(s2); s3 = warpSum(s3);
    float i0 = 1.f / (s0 + 1e-16f), i1 = 1.f / (s1 + 1e-16f);
    float i2 = 1.f / (s2 + 1e-16f), i3 = 1.f / (s3 + 1e-16f);

    int head = lane >> 3;
    float mh  = head < 2 ? (head == 0 ? m0 : m1) : (head == 2 ? m2 : m3);
    float ih  = head < 2 ? (head == 0 ? i0 : i1) : (head == 2 ? i2 : i3);
    float adh = head < 2 ? (head == 0 ? ad.x : ad.y) : (head == 2 ? ad.z : ad.w);

    float acc[8];
    #pragma unroll
    for (int k = 0; k < 8; k++) acc[k] = 0.f;

    for (int e = beg; e < end; ++e) {
        int s = g_csr[e];
        float w = expf(lrelu(g_asrc1[s * 4 + head] + adh) - mh) * ih;
        uint4 raw = *(const uint4*)(g_h1h + (size_t)s * 256 + lane * 8);
        const __half2* hp = (const __half2*)&raw;
        #pragma unroll
        for (int q = 0; q < 4; q++) {
            float2 f = __half22float2(hp[q]);
            acc[q * 2]     = fmaf(w, f.x, acc[q * 2]);
            acc[q * 2 + 1] = fmaf(w, f.y, acc[q * 2 + 1]);
        }
    }
    const float* bb = b1 + lane * 8;
    __half2 o[4];
    #pragma unroll
    for (int q = 0; q < 4; q++) {
        float r0 = acc[q * 2]     + bb[q * 2];
        float r1 = acc[q * 2 + 1] + bb[q * 2 + 1];
        r0 = r0 > 0.f ? r0 : (expf(r0) - 1.f);
        r1 = r1 > 0.f ? r1 : (expf(r1) - 1.f);
        o[q] = __floats2half2_rn(r0, r1);
    }
    *(uint4*)(g_e1h + (size_t)node * 256 + lane * 8) = *(const uint4*)o;
}

// ---------------- attention coefficients, layer 2 (H=1, C=64) ----------------
__global__ void attn2(const float* __restrict__ att_src, const float* __restrict__ att_dst) {
    int node = blockIdx.x * 8 + (threadIdx.x >> 5);
    if (node >= NN) return;
    int lane = threadIdx.x & 31;
    float2 v = __half22float2(*(const __half2*)(g_h2h + (size_t)node * 64 + lane * 2));
    float ps = v.x * att_src[lane * 2] + v.y * att_src[lane * 2 + 1];
    float pd = v.x * att_dst[lane * 2] + v.y * att_dst[lane * 2 + 1];
    ps = warpSum(ps);
    pd = warpSum(pd);
    if (lane == 0) {
        g_asrc2[node] = ps;
        g_adst2[node] = pd;
    }
}

// ---------------- layer-2 aggregation ----------------
__global__ __launch_bounds__(256) void aggregate2(const float* __restrict__ b2) {
    int node = blockIdx.x * 8 + (threadIdx.x >> 5);
    if (node >= NN) return;
    int lane = threadIdx.x & 31;
    int beg = g_rowptr[node], end = g_rowptr[node + 1];
    float adv = g_adst2[node];

    float m = -1e30f;
    for (int e = beg + lane; e < end; e += 32)
        m = fmaxf(m, lrelu(g_asrc2[g_csr[e]] + adv));
    m = warpMax(m);
    float sm = 0.f;
    for (int e = beg + lane; e < end; e += 32)
        sm += expf(lrelu(g_asrc2[g_csr[e]] + adv) - m);
    sm = warpSum(sm);
    float inv = 1.f / (sm + 1e-16f);

    float a0 = 0.f, a1 = 0.f;
    for (int e = beg; e < end; ++e) {
        int s = g_csr[e];
        float w = expf(lrelu(g_asrc2[s] + adv) - m) * inv;
        float2 v = __half22float2(*(const __half2*)(g_h2h + (size_t)s * 64 + lane * 2));
        a0 = fmaf(w, v.x, a0);
        a1 = fmaf(w, v.y, a1);
    }
    g_o2[(size_t)node * 64 + lane * 2]     = a0 + b2[lane * 2];
    g_o2[(size_t)node * 64 + lane * 2 + 1] = a1 + b2[lane * 2 + 1];
}

// ---------------- global mean pool (batch is sorted) ----------------
__device__ __forceinline__ int lower_bound_i(const int* b, int n, int v) {
    int lo = 0, hi = n;
    while (lo < hi) {
        int mid = (lo + hi) >> 1;
        if (b[mid] < v) lo = mid + 1; else hi = mid;
    }
    return lo;
}
__global__ void pool(const int* __restrict__ batch) {
    __shared__ float part[256];
    __shared__ int sb, se;
    int g = blockIdx.x;
    if (threadIdx.x == 0) {
        sb = lower_bound_i(batch, NN, g);
        se = lower_bound_i(batch, NN, g + 1);
    }
    __syncthreads();
    int c = threadIdx.x & 63, q = threadIdx.x >> 6;
    float s = 0.f;
    for (int i = sb + q; i < se; i += 4) s += g_o2[(size_t)i * 64 + c];
    part[threadIdx.x] = s;
    __syncthreads();
    if (q == 0) {
        float t = part[c] + part[c + 64] + part[c + 128] + part[c + 192];
        float cnt = (float)(se - sb);
        g_emb[g * 64 + c] = t / fmaxf(cnt, 1.f);
    }
}

// ---------------- final MLP ----------------
__global__ void mlp(const float* __restrict__ W3, const float* __restrict__ b3,
                    const float* __restrict__ W4, const float* __restrict__ b4,
                    float* __restrict__ out) {
    __shared__ float w3[64 * 32], w4[64], bb3[32], bb4[2];
    int t = threadIdx.x;
    for (int i = t; i < 2048; i += 64) w3[i] = W3[i];
    w4[t] = W4[t];
    if (t < 32) bb3[t] = b3[t];
    if (t < 2) bb4[t] = b4[t];
    __syncthreads();
    float e[64];
    #pragma unroll
    for (int k = 0; k < 64; k++) e[k] = g_emb[t * 64 + k];
    float l0 = bb4[0], l1 = bb4[1];
    #pragma unroll 4
    for (int j = 0; j < 32; j++) {
        float z = bb3[j];
        #pragma unroll
        for (int k = 0; k < 64; k++) z = fmaf(e[k], w3[k * 32 + j], z);
        z = fmaxf(z, 0.f);
        l0 = fmaf(z, w4[j * 2], l0);
        l1 = fmaf(z, w4[j * 2 + 1], l1);
    }
    out[t * 2] = l0;
    out[t * 2 + 1] = l1;
}

// ---------------- launch ----------------
extern "C" void kernel_launch(void* const* d_in, const int* in_sizes, int n_in,
                              void* d_out, int out_size) {
    const float* x = (const float*)d_in[0];
    const int* ei = (const int*)d_in[1];
    const int* batch = (const int*)d_in[2];
    const float* W1 = (const float*)d_in[3];
    const float* as1 = (const float*)d_in[4];
    const float* ad1 = (const float*)d_in[5];
    const float* b1 = (const float*)d_in[6];
    const float* W2 = (const float*)d_in[7];
    const float* as2 = (const float*)d_in[8];
    const float* ad2 = (const float*)d_in[9];
    const float* b2 = (const float*)d_in[10];
    const float* W3 = (const float*)d_in[11];
    const float* b3 = (const float*)d_in[12];
    const float* W4 = (const float*)d_in[13];
    const float* b4 = (const float*)d_in[14];
    float* out = (float*)d_out;

    const int* e_src = ei;
    const int* e_dst = ei + EE;

    void* p;
    cudaGetSymbolAddress(&p, g_h1h);  __half* h1 = (__half*)p;
    cudaGetSymbolAddress(&p, g_e1h);  __half* e1 = (__half*)p;
    cudaGetSymbolAddress(&p, g_h2h);  __half* h2 = (__half*)p;

    const int agg_blocks = NN / 8;  // 12500, exact

    // GEMM1 sits in the ncu capture slot (4th launch).
    init_cnt<<<(NN + 255) / 256, 256>>>();
    count_edges<<<(EE + 255) / 256, 256>>>(e_dst);
    scan1<<<NBLK_SCAN, SCAN_BLK>>>();
    // GEMM1: h1 = x @ W1  [100000,256] (fp16 HMMA, double-buffered)
    gemm_h<false><<<dim3(4, 782), 256>>>(x, W1, h1, NN, 256, 256);
    scan2<<<1, 32>>>();
    scan3<<<(NN + 255) / 256, 256>>>();
    scatter_edges<<<(EE + NN + 255) / 256, 256>>>(e_src, e_dst);
    attn1<<<agg_blocks, 256>>>(as1, ad1);
    // layer-1 softmax-aggregate + ELU (fp16 gather + fp16 out)
    aggregate1<<<agg_blocks, 256>>>(b1);
    // GEMM2: h2 = e1 @ W2  [100000,64] (fp16 A direct)
    gemm_h<true><<<dim3(1, 782), 256>>>(e1, W2, h2, NN, 256, 64);
    attn2<<<agg_blocks, 256>>>(as2, ad2);
    aggregate2<<<agg_blocks, 256>>>(b2);
    // mean pool + MLP head
    pool<<<GG, 256>>>(batch);
    mlp<<<1, 64>>>(W3, b3, W4, b4, out);
}

// round 8
// speedup vs baseline: 1.9468x; 1.0766x over previous
#include <cuda_runtime.h>
#include <cuda_fp16.h>
#include <stdint.h>
#include <math.h>

#define NN 100000
#define EE 1600000
#define GG 64
#define SCAN_BLK 1024
#define NBLK_SCAN ((NN + SCAN_BLK - 1) / SCAN_BLK)   // 98

// ---------------- scratch (device globals; no allocation) ----------------
__device__ __align__(16) __half g_h1h[(size_t)NN * 256];  // x @ W1 (fp16)
__device__ __align__(16) __half g_e1h[(size_t)NN * 256];  // elu(aggregate1) (fp16)
__device__ __align__(16) __half g_h2h[(size_t)NN * 64];   // e1 @ W2 (fp16)
__device__ __align__(16) __half g_w1h[256 * 256];         // W1 fp16
__device__ __align__(16) __half g_w2h[256 * 64];          // W2 fp16
__device__ __align__(16) float g_o2[(size_t)NN * 64];     // aggregate2 (fp32)
__device__ __align__(16) float g_asrc1[NN * 4];
__device__ __align__(16) float g_adst1[NN * 4];
__device__ float g_asrc2[NN];
__device__ float g_adst2[NN];
__device__ int   g_cnt[NN];
__device__ int   g_rowptr[NN + 1];
__device__ int   g_wpos[NN];
__device__ int   g_csr[EE + NN];
__device__ int   g_part[NBLK_SCAN + 8];
__device__ float g_emb[GG * 64];

// ---------------- helpers ----------------
__device__ __forceinline__ float warpMax(float v) {
    #pragma unroll
    for (int o = 16; o; o >>= 1) v = fmaxf(v, __shfl_xor_sync(0xffffffffu, v, o));
    return v;
}
__device__ __forceinline__ float warpSum(float v) {
    #pragma unroll
    for (int o = 16; o; o >>= 1) v += __shfl_xor_sync(0xffffffffu, v, o);
    return v;
}
__device__ __forceinline__ float lrelu(float a) { return a > 0.f ? a : 0.2f * a; }
__device__ __forceinline__ uint32_t smem_u32(const void* p) {
    return (uint32_t)__cvta_generic_to_shared(p);
}
#define CP_ASYNC16(saddr, gptr) \
    asm volatile("cp.async.cg.shared.global [%0], [%1], 16;" :: "r"(saddr), "l"(gptr))
#define CP_COMMIT() asm volatile("cp.async.commit_group;")
#define CP_WAIT0()  asm volatile("cp.async.wait_group 0;")

// ---------------- prep: init cnt + convert W1/W2 to fp16 ----------------
__global__ void prep(const float* __restrict__ W1, const float* __restrict__ W2) {
    int i = blockIdx.x * blockDim.x + threadIdx.x;
    if (i < NN) g_cnt[i] = 1;  // self loop
    if (i < 256 * 256) g_w1h[i] = __float2half_rn(W1[i]);
    if (i < 256 * 64)  g_w2h[i] = __float2half_rn(W2[i]);
}

// ---------------- FP16 tensor-core GEMM, double-buffered, cp.async B ------
// C[M,Ncol] = A[M,K] @ B[K,Ncol]. A fp32 (cvt-staged) or fp16 (cp.async);
// B fp16 (cp.async); C fp16. BM=128, BK=32, BN template (64 or 128).
// 8 warps: 4 along M x 2 along N; warp tile 32 x BN/2.
#define APAD 8
#define BPAD 8
template <int BN, bool HALF_A>
__global__ __launch_bounds__(256)
void gemm_h(const void* __restrict__ Av, const __half* __restrict__ B,
            __half* __restrict__ C, int M, int K, int Ncol) {
    const int BM = 128, BK = 32;
    const int NT = BN / 16;   // mma n-tiles per warp
    const int NB = BN / 32;   // B ldmatrix.x4 per 16-k chunk
    __shared__ __half Ah[2][BM][BK + APAD];
    __shared__ __half Bs[2][BK][BN + BPAD];

    const int tid = threadIdx.x;
    const int warp = tid >> 5, lane = tid & 31;
    const int warpM = warp & 3, warpN = warp >> 2;
    const int rowBase = blockIdx.y * BM;
    const int colBase = blockIdx.x * BN;
    const int gid = lane >> 2;
    const int tig = lane & 3;

    float c[2][NT][4];
    #pragma unroll
    for (int mt = 0; mt < 2; mt++)
        #pragma unroll
        for (int nt = 0; nt < NT; nt++)
            #pragma unroll
            for (int r = 0; r < 4; r++) c[mt][nt][r] = 0.f;

    float4 raf[4];   // fp32 A staging

    const int nk = K / BK;

    auto ldgA = [&](int kt) {
        if (!HALF_A) {
            const float* A = (const float*)Av;
            int k0 = kt * BK;
            #pragma unroll
            for (int it = 0; it < 4; it++) {
                int i = tid + it * 256;
                int r = i >> 3, q = i & 7;
                raf[it] = make_float4(0.f, 0.f, 0.f, 0.f);
                if (rowBase + r < M)
                    raf[it] = *(const float4*)(A + (size_t)(rowBase + r) * K + k0 + q * 4);
            }
        }
    };
    auto stsA = [&](int buf) {
        if (!HALF_A) {
            #pragma unroll
            for (int it = 0; it < 4; it++) {
                int i = tid + it * 256;
                int r = i >> 3, q = i & 7;
                __half2 h[2];
                h[0] = __floats2half2_rn(raf[it].x, raf[it].y);
                h[1] = __floats2half2_rn(raf[it].z, raf[it].w);
                *(uint2*)&Ah[buf][r][q * 4] = *(const uint2*)h;
            }
        }
    };
    auto asyncA = [&](int kt, int buf) {   // fp16 A via cp.async
        if (HALF_A) {
            const __half* A = (const __half*)Av;
            int k0 = kt * BK;
            #pragma unroll
            for (int it = 0; it < 2; it++) {
                int i = tid + it * 256;
                int r = i >> 2, q = i & 3;
                if (rowBase + r < M)
                    CP_ASYNC16(smem_u32(&Ah[buf][r][q * 8]),
                               A + (size_t)(rowBase + r) * K + k0 + q * 8);
            }
        }
    };
    auto asyncB = [&](int kt, int buf) {
        int k0 = kt * BK;
        // BK x BN halves = 64*BN bytes; per thread BN/4 bytes
        #pragma unroll
        for (int it = 0; it < BN / 64; it++) {
            int i = tid + it * 256;
            int r = i / (BN / 8), q = i % (BN / 8);
            CP_ASYNC16(smem_u32(&Bs[buf][r][q * 8]),
                       B + (size_t)(k0 + r) * Ncol + colBase + q * 8);
        }
    };
    auto compute = [&](int buf) {
        #pragma unroll
        for (int ks = 0; ks < BK; ks += 16) {
            uint32_t a[2][4];
            #pragma unroll
            for (int mt = 0; mt < 2; mt++) {
                int lrow = warpM * 32 + mt * 16 + (lane & 15);
                int lcol = ks + ((lane >> 4) << 3);
                uint32_t addr = smem_u32(&Ah[buf][lrow][lcol]);
                asm volatile(
                    "ldmatrix.sync.aligned.m8n8.x4.shared.b16 {%0,%1,%2,%3}, [%4];"
                    : "=r"(a[mt][0]), "=r"(a[mt][1]), "=r"(a[mt][2]), "=r"(a[mt][3])
                    : "r"(addr));
            }
            uint32_t b[NT][2];
            #pragma unroll
            for (int hb = 0; hb < NB; hb++) {
                int krow = ks + (lane & 15);
                int ncol = warpN * (BN / 2) + hb * 16 + ((lane >> 4) << 3);
                uint32_t addr = smem_u32(&Bs[buf][krow][ncol]);
                uint32_t r0, r1, r2, r3;
                asm volatile(
                    "ldmatrix.sync.aligned.m8n8.x4.trans.shared.b16 {%0,%1,%2,%3}, [%4];"
                    : "=r"(r0), "=r"(r1), "=r"(r2), "=r"(r3)
                    : "r"(addr));
                b[hb * 2 + 0][0] = r0; b[hb * 2 + 0][1] = r1;
                b[hb * 2 + 1][0] = r2; b[hb * 2 + 1][1] = r3;
            }
            #pragma unroll
            for (int mt = 0; mt < 2; mt++)
                #pragma unroll
                for (int nt = 0; nt < NT; nt++) {
                    asm volatile(
                        "mma.sync.aligned.m16n8k16.row.col.f32.f16.f16.f32 "
                        "{%0,%1,%2,%3}, {%4,%5,%6,%7}, {%8,%9}, {%0,%1,%2,%3};"
                        : "+f"(c[mt][nt][0]), "+f"(c[mt][nt][1]),
                          "+f"(c[mt][nt][2]), "+f"(c[mt][nt][3])
                        : "r"(a[mt][0]), "r"(a[mt][1]), "r"(a[mt][2]), "r"(a[mt][3]),
                          "r"(b[nt][0]), "r"(b[nt][1]));
                }
        }
    };

    // prologue
    asyncB(0, 0); asyncA(0, 0); CP_COMMIT();
    ldgA(0); stsA(0);
    CP_WAIT0();
    __syncthreads();
    for (int kt = 0; kt < nk; kt++) {
        int buf = kt & 1;
        if (kt + 1 < nk) {
            asyncB(kt + 1, buf ^ 1);
            asyncA(kt + 1, buf ^ 1);
            CP_COMMIT();
            ldgA(kt + 1);
        }
        compute(buf);
        if (kt + 1 < nk) {
            stsA(buf ^ 1);
            CP_WAIT0();
            __syncthreads();
        }
    }

    #pragma unroll
    for (int mt = 0; mt < 2; mt++) {
        int row0 = rowBase + warpM * 32 + mt * 16 + gid;
        #pragma unroll
        for (int nt = 0; nt < NT; nt++) {
            int col = colBase + warpN * (BN / 2) + nt * 8 + tig * 2;
            if (row0 < M)
                *(__half2*)(C + (size_t)row0 * Ncol + col) =
                    __floats2half2_rn(c[mt][nt][0], c[mt][nt][1]);
            if (row0 + 8 < M)
                *(__half2*)(C + (size_t)(row0 + 8) * Ncol + col) =
                    __floats2half2_rn(c[mt][nt][2], c[mt][nt][3]);
        }
    }
}

// ---------------- attention coefficients, layer 1 (H=4, C=64) ----------------
__global__ void attn1(const float* __restrict__ att_src, const float* __restrict__ att_dst) {
    int node = blockIdx.x * 8 + (threadIdx.x >> 5);
    if (node >= NN) return;
    int lane = threadIdx.x & 31;
    int head = lane >> 3;
    int sub = lane & 7;
    uint4 raw = *(const uint4*)(g_h1h + (size_t)node * 256 + lane * 8);
    const __half2* hp = (const __half2*)&raw;
    float h[8];
    #pragma unroll
    for (int q = 0; q < 4; q++) {
        float2 f = __half22float2(hp[q]);
        h[q * 2] = f.x; h[q * 2 + 1] = f.y;
    }
    const float* asp = att_src + head * 64 + sub * 8;
    const float* adp = att_dst + head * 64 + sub * 8;
    float ps = 0.f, pd = 0.f;
    #pragma unroll
    for (int q = 0; q < 8; q++) {
        ps = fmaf(h[q], asp[q], ps);
        pd = fmaf(h[q], adp[q], pd);
    }
    #pragma unroll
    for (int o = 4; o; o >>= 1) {
        ps += __shfl_down_sync(0xffffffffu, ps, o, 8);
        pd += __shfl_down_sync(0xffffffffu, pd, o, 8);
    }
    if (sub == 0) {
        g_asrc1[node * 4 + head] = ps;
        g_adst1[node * 4 + head] = pd;
    }
}

// ---------------- CSR build ----------------
__global__ void count_edges(const int* __restrict__ dst) {
    int e = blockIdx.x * blockDim.x + threadIdx.x;
    if (e < EE) atomicAdd(&g_cnt[dst[e]], 1);
}
__global__ void scan1() {
    __shared__ int wsum[32];
    int i = blockIdx.x * SCAN_BLK + threadIdx.x;
    int v = (i < NN) ? g_cnt[i] : 0;
    int lane = threadIdx.x & 31, wid = threadIdx.x >> 5;
    int incl = v;
    #pragma unroll
    for (int o = 1; o < 32; o <<= 1) {
        int t = __shfl_up_sync(0xffffffffu, incl, o);
        if (lane >= o) incl += t;
    }
    if (lane == 31) wsum[wid] = incl;
    __syncthreads();
    if (wid == 0) {
        int s = wsum[lane];
        #pragma unroll
        for (int o = 1; o < 32; o <<= 1) {
            int t = __shfl_up_sync(0xffffffffu, s, o);
            if (lane >= o) s += t;
        }
        wsum[lane] = s;
    }
    __syncthreads();
    int base = (wid > 0) ? wsum[wid - 1] : 0;
    incl += base;
    if (i < NN) g_rowptr[i] = incl - v;
    if (threadIdx.x == SCAN_BLK - 1) g_part[blockIdx.x] = incl;
}
__global__ void scan2() {
    if (threadIdx.x == 0) {
        int run = 0;
        for (int b = 0; b < NBLK_SCAN; b++) {
            int t = g_part[b];
            g_part[b] = run;
            run += t;
        }
        g_rowptr[NN] = run;
    }
}
__global__ void scan3() {
    int i = blockIdx.x * blockDim.x + threadIdx.x;
    if (i < NN) {
        int r = g_rowptr[i] + g_part[i >> 10];
        g_rowptr[i] = r;
        g_wpos[i] = r;
    }
}
__global__ void scatter_edges(const int* __restrict__ src, const int* __restrict__ dst) {
    int e = blockIdx.x * blockDim.x + threadIdx.x;
    if (e < EE) {
        int d = dst[e];
        int pos = atomicAdd(&g_wpos[d], 1);
        g_csr[pos] = src[e];
    } else if (e < EE + NN) {
        int i = e - EE;
        int pos = atomicAdd(&g_wpos[i], 1);
        g_csr[pos] = i;
    }
}

// ---------------- layer-1 aggregation: warp per dst node ----------------
__global__ __launch_bounds__(256) void aggregate1(const float* __restrict__ b1) {
    int node = blockIdx.x * 8 + (threadIdx.x >> 5);
    if (node >= NN) return;
    int lane = threadIdx.x & 31;
    int beg = g_rowptr[node], end = g_rowptr[node + 1];
    float4 ad = *(const float4*)(g_adst1 + node * 4);

    float m0 = -1e30f, m1 = -1e30f, m2 = -1e30f, m3 = -1e30f;
    for (int e = beg + lane; e < end; e += 32) {
        int s = g_csr[e];
        float4 as = *(const float4*)(g_asrc1 + s * 4);
        m0 = fmaxf(m0, lrelu(as.x + ad.x));
        m1 = fmaxf(m1, lrelu(as.y + ad.y));
        m2 = fmaxf(m2, lrelu(as.z + ad.z));
        m3 = fmaxf(m3, lrelu(as.w + ad.w));
    }
    m0 = warpMax(m0); m1 = warpMax(m1); m2 = warpMax(m2); m3 = warpMax(m3);

    float s0 = 0.f, s1 = 0.f, s2 = 0.f, s3 = 0.f;
    for (int e = beg + lane; e < end; e += 32) {
        int s = g_csr[e];
        float4 as = *(const float4*)(g_asrc1 + s * 4);
        s0 += expf(lrelu(as.x + ad.x) - m0);
        s1 += expf(lrelu(as.y + ad.y) - m1);
        s2 += expf(lrelu(as.z + ad.z) - m2);
        s3 += expf(lrelu(as.w + ad.w) - m3);
    }
    s0 = warpSum(s0); s1 = warpSum(s1); s2 = warpSum(s2); s3 = warpSum(s3);
    float i0 = 1.f / (s0 + 1e-16f), i1 = 1.f / (s1 + 1e-16f);
    float i2 = 1.f / (s2 + 1e-16f), i3 = 1.f / (s3 + 1e-16f);

    int head = lane >> 3;
    float mh  = head < 2 ? (head == 0 ? m0 : m1) : (head == 2 ? m2 : m3);
    float ih  = head < 2 ? (head == 0 ? i0 : i1) : (head == 2 ? i2 : i3);
    float adh = head < 2 ? (head == 0 ? ad.x : ad.y) : (head == 2 ? ad.z : ad.w);

    float acc[8];
    #pragma unroll
    for (int k = 0; k < 8; k++) acc[k] = 0.f;

    for (int e = beg; e < end; ++e) {
        int s = g_csr[e];
        float w = expf(lrelu(g_asrc1[s * 4 + head] + adh) - mh) * ih;
        uint4 raw = *(const uint4*)(g_h1h + (size_t)s * 256 + lane * 8);
        const __half2* hp = (const __half2*)&raw;
        #pragma unroll
        for (int q = 0; q < 4; q++) {
            float2 f = __half22float2(hp[q]);
            acc[q * 2]     = fmaf(w, f.x, acc[q * 2]);
            acc[q * 2 + 1] = fmaf(w, f.y, acc[q * 2 + 1]);
        }
    }
    const float* bb = b1 + lane * 8;
    __half2 o[4];
    #pragma unroll
    for (int q = 0; q < 4; q++) {
        float r0 = acc[q * 2]     + bb[q * 2];
        float r1 = acc[q * 2 + 1] + bb[q * 2 + 1];
        r0 = r0 > 0.f ? r0 : (expf(r0) - 1.f);
        r1 = r1 > 0.f ? r1 : (expf(r1) - 1.f);
        o[q] = __floats2half2_rn(r0, r1);
    }
    *(uint4*)(g_e1h + (size_t)node * 256 + lane * 8) = *(const uint4*)o;
}

// ---------------- attention coefficients, layer 2 (H=1, C=64) ----------------
__global__ void attn2(const float* __restrict__ att_src, const float* __restrict__ att_dst) {
    int node = blockIdx.x * 8 + (threadIdx.x >> 5);
    if (node >= NN) return;
    int lane = threadIdx.x & 31;
    float2 v = __half22float2(*(const __half2*)(g_h2h + (size_t)node * 64 + lane * 2));
    float ps = v.x * att_src[lane * 2] + v.y * att_src[lane * 2 + 1];
    float pd = v.x * att_dst[lane * 2] + v.y * att_dst[lane * 2 + 1];
    ps = warpSum(ps);
    pd = warpSum(pd);
    if (lane == 0) {
        g_asrc2[node] = ps;
        g_adst2[node] = pd;
    }
}

// ---------------- layer-2 aggregation ----------------
__global__ __launch_bounds__(256) void aggregate2(const float* __restrict__ b2) {
    int node = blockIdx.x * 8 + (threadIdx.x >> 5);
    if (node >= NN) return;
    int lane = threadIdx.x & 31;
    int beg = g_rowptr[node], end = g_rowptr[node + 1];
    float adv = g_adst2[node];

    float m = -1e30f;
    for (int e = beg + lane; e < end; e += 32)
        m = fmaxf(m, lrelu(g_asrc2[g_csr[e]] + adv));
    m = warpMax(m);
    float sm = 0.f;
    for (int e = beg + lane; e < end; e += 32)
        sm += expf(lrelu(g_asrc2[g_csr[e]] + adv) - m);
    sm = warpSum(sm);
    float inv = 1.f / (sm + 1e-16f);

    float a0 = 0.f, a1 = 0.f;
    for (int e = beg; e < end; ++e) {
        int s = g_csr[e];
        float w = expf(lrelu(g_asrc2[s] + adv) - m) * inv;
        float2 v = __half22float2(*(const __half2*)(g_h2h + (size_t)s * 64 + lane * 2));
        a0 = fmaf(w, v.x, a0);
        a1 = fmaf(w, v.y, a1);
    }
    g_o2[(size_t)node * 64 + lane * 2]     = a0 + b2[lane * 2];
    g_o2[(size_t)node * 64 + lane * 2 + 1] = a1 + b2[lane * 2 + 1];
}

// ---------------- global mean pool (batch is sorted) ----------------
__device__ __forceinline__ int lower_bound_i(const int* b, int n, int v) {
    int lo = 0, hi = n;
    while (lo < hi) {
        int mid = (lo + hi) >> 1;
        if (b[mid] < v) lo = mid + 1; else hi = mid;
    }
    return lo;
}
__global__ void pool(const int* __restrict__ batch) {
    __shared__ float part[256];
    __shared__ int sb, se;
    int g = blockIdx.x;
    if (threadIdx.x == 0) {
        sb = lower_bound_i(batch, NN, g);
        se = lower_bound_i(batch, NN, g + 1);
    }
    __syncthreads();
    int c = threadIdx.x & 63, q = threadIdx.x >> 6;
    float s = 0.f;
    for (int i = sb + q; i < se; i += 4) s += g_o2[(size_t)i * 64 + c];
    part[threadIdx.x] = s;
    __syncthreads();
    if (q == 0) {
        float t = part[c] + part[c + 64] + part[c + 128] + part[c + 192];
        float cnt = (float)(se - sb);
        g_emb[g * 64 + c] = t / fmaxf(cnt, 1.f);
    }
}

// ---------------- final MLP ----------------
__global__ void mlp(const float* __restrict__ W3, const float* __restrict__ b3,
                    const float* __restrict__ W4, const float* __restrict__ b4,
                    float* __restrict__ out) {
    __shared__ float w3[64 * 32], w4[64], bb3[32], bb4[2];
    int t = threadIdx.x;
    for (int i = t; i < 2048; i += 64) w3[i] = W3[i];
    w4[t] = W4[t];
    if (t < 32) bb3[t] = b3[t];
    if (t < 2) bb4[t] = b4[t];
    __syncthreads();
    float e[64];
    #pragma unroll
    for (int k = 0; k < 64; k++) e[k] = g_emb[t * 64 + k];
    float l0 = bb4[0], l1 = bb4[1];
    #pragma unroll 4
    for (int j = 0; j < 32; j++) {
        float z = bb3[j];
        #pragma unroll
        for (int k = 0; k < 64; k++) z = fmaf(e[k], w3[k * 32 + j], z);
        z = fmaxf(z, 0.f);
        l0 = fmaf(z, w4[j * 2], l0);
        l1 = fmaf(z, w4[j * 2 + 1], l1);
    }
    out[t * 2] = l0;
    out[t * 2 + 1] = l1;
}

// ---------------- launch ----------------
extern "C" void kernel_launch(void* const* d_in, const int* in_sizes, int n_in,
                              void* d_out, int out_size) {
    const float* x = (const float*)d_in[0];
    const int* ei = (const int*)d_in[1];
    const int* batch = (const int*)d_in[2];
    const float* W1 = (const float*)d_in[3];
    const float* as1 = (const float*)d_in[4];
    const float* ad1 = (const float*)d_in[5];
    const float* b1 = (const float*)d_in[6];
    const float* W2 = (const float*)d_in[7];
    const float* as2 = (const float*)d_in[8];
    const float* ad2 = (const float*)d_in[9];
    const float* b2 = (const float*)d_in[10];
    const float* W3 = (const float*)d_in[11];
    const float* b3 = (const float*)d_in[12];
    const float* W4 = (const float*)d_in[13];
    const float* b4 = (const float*)d_in[14];
    float* out = (float*)d_out;

    const int* e_src = ei;
    const int* e_dst = ei + EE;

    void* p;
    cudaGetSymbolAddress(&p, g_h1h);  __half* h1 = (__half*)p;
    cudaGetSymbolAddress(&p, g_e1h);  __half* e1 = (__half*)p;
    cudaGetSymbolAddress(&p, g_h2h);  __half* h2 = (__half*)p;
    cudaGetSymbolAddress(&p, g_w1h);  __half* w1h = (__half*)p;
    cudaGetSymbolAddress(&p, g_w2h);  __half* w2h = (__half*)p;

    const int agg_blocks = NN / 8;  // 12500, exact

    // GEMM1 sits in the ncu capture slot (4th launch).
    prep<<<(NN + 255) / 256, 256>>>(W1, W2);   // cnt=1 + W->fp16
    count_edges<<<(EE + 255) / 256, 256>>>(e_dst);
    scan1<<<NBLK_SCAN, SCAN_BLK>>>();
    // GEMM1: h1 = x @ W1  [100000,256] (BN=128, cp.async B)
    gemm_h<128, false><<<dim3(2, 782), 256>>>(x, w1h, h1, NN, 256, 256);
    scan2<<<1, 32>>>();
    scan3<<<(NN + 255) / 256, 256>>>();
    scatter_edges<<<(EE + NN + 255) / 256, 256>>>(e_src, e_dst);
    attn1<<<agg_blocks, 256>>>(as1, ad1);
    // layer-1 softmax-aggregate + ELU (fp16 gather + fp16 out)
    aggregate1<<<agg_blocks, 256>>>(b1);
    // GEMM2: h2 = e1 @ W2  [100000,64] (fp16 A via cp.async)
    gemm_h<64, true><<<dim3(1, 782), 256>>>(e1, w2h, h2, NN, 256, 64);
    attn2<<<agg_blocks, 256>>>(as2, ad2);
    aggregate2<<<agg_blocks, 256>>>(b2);
    // mean pool + MLP head
    pool<<<GG, 256>>>(batch);
    mlp<<<1, 64>>>(W3, b3, W4, b4, out);
}

// round 9
// speedup vs baseline: 2.2146x; 1.1375x over previous
#include <cuda_runtime.h>
#include <cuda_fp16.h>
#include <stdint.h>
#include <math.h>

#define NN 100000
#define EE 1600000
#define GG 64
#define SCAN_BLK 1024
#define NBLK_SCAN ((NN + SCAN_BLK - 1) / SCAN_BLK)   // 98

// ---------------- scratch (device globals; no allocation) ----------------
__device__ __align__(16) __half g_h1h[(size_t)NN * 256];  // x @ W1 (fp16)
__device__ __align__(16) __half g_e1h[(size_t)NN * 256];  // elu(aggregate1) (fp16)
__device__ __align__(16) __half g_h2h[(size_t)NN * 64];   // e1 @ W2 (fp16)
__device__ __align__(16) __half g_w1h[256 * 256];         // W1 fp16
__device__ __align__(16) __half g_w2h[256 * 64];          // W2 fp16
__device__ __align__(16) float g_o2[(size_t)NN * 64];     // aggregate2 (fp32)
__device__ __align__(16) float g_asrc1[NN * 4];
__device__ __align__(16) float g_adst1[NN * 4];
__device__ float g_asrc2[NN];
__device__ float g_adst2[NN];
__device__ int   g_cnt[NN];
__device__ int   g_rowptr[NN + 1];
__device__ int   g_wpos[NN];
__device__ int   g_csr[EE + NN];
__device__ int   g_part[NBLK_SCAN + 8];
__device__ float g_emb[GG * 64];

// ---------------- helpers ----------------
__device__ __forceinline__ float warpMax(float v) {
    #pragma unroll
    for (int o = 16; o; o >>= 1) v = fmaxf(v, __shfl_xor_sync(0xffffffffu, v, o));
    return v;
}
__device__ __forceinline__ float warpSum(float v) {
    #pragma unroll
    for (int o = 16; o; o >>= 1) v += __shfl_xor_sync(0xffffffffu, v, o);
    return v;
}
__device__ __forceinline__ float lrelu(float a) { return a > 0.f ? a : 0.2f * a; }
__device__ __forceinline__ uint32_t smem_u32(const void* p) {
    return (uint32_t)__cvta_generic_to_shared(p);
}
#define CP_ASYNC16(saddr, gptr) \
    asm volatile("cp.async.cg.shared.global [%0], [%1], 16;" :: "r"(saddr), "l"(gptr))
#define CP_COMMIT() asm volatile("cp.async.commit_group;")
#define CP_WAIT0()  asm volatile("cp.async.wait_group 0;")

// ---------------- prepW: convert W1/W2 to fp16 ----------------
__global__ void prepW(const float* __restrict__ W1, const float* __restrict__ W2) {
    int i = blockIdx.x * blockDim.x + threadIdx.x;
    if (i < 256 * 256) g_w1h[i] = __float2half_rn(W1[i]);
    if (i < 256 * 64)  g_w2h[i] = __float2half_rn(W2[i]);
}

// ---------------- FP16 tensor-core GEMM, double-buffered, cp.async --------
// C[M,Ncol] = A[M,K] @ B[K,Ncol]. A fp32 (cvt-staged) or fp16 (cp.async);
// B fp16 (cp.async); C fp16. BM=128, BK=32, BN template.
// ATT1: fuse per-row attention dots (asrc1/adst1) into the epilogue
// (valid for BN=128, Ncol=256, grid(2,*): each warp slice == one head).
#define APAD 8
#define BPAD 8
template <int BN, bool HALF_A, bool ATT1>
__global__ __launch_bounds__(256)
void gemm_h(const void* __restrict__ Av, const __half* __restrict__ B,
            __half* __restrict__ C, int M, int K, int Ncol,
            const float* __restrict__ att_src, const float* __restrict__ att_dst) {
    const int BM = 128, BK = 32;
    const int NT = BN / 16;
    const int NB = BN / 32;
    __shared__ __half Ah[2][BM][BK + APAD];
    __shared__ __half Bs[2][BK][BN + BPAD];

    const int tid = threadIdx.x;
    const int warp = tid >> 5, lane = tid & 31;
    const int warpM = warp & 3, warpN = warp >> 2;
    const int rowBase = blockIdx.y * BM;
    const int colBase = blockIdx.x * BN;
    const int gid = lane >> 2;
    const int tig = lane & 3;

    float c[2][NT][4];
    #pragma unroll
    for (int mt = 0; mt < 2; mt++)
        #pragma unroll
        for (int nt = 0; nt < NT; nt++)
            #pragma unroll
            for (int r = 0; r < 4; r++) c[mt][nt][r] = 0.f;

    float4 raf[4];

    const int nk = K / BK;

    auto ldgA = [&](int kt) {
        if (!HALF_A) {
            const float* A = (const float*)Av;
            int k0 = kt * BK;
            #pragma unroll
            for (int it = 0; it < 4; it++) {
                int i = tid + it * 256;
                int r = i >> 3, q = i & 7;
                raf[it] = make_float4(0.f, 0.f, 0.f, 0.f);
                if (rowBase + r < M)
                    raf[it] = *(const float4*)(A + (size_t)(rowBase + r) * K + k0 + q * 4);
            }
        }
    };
    auto stsA = [&](int buf) {
        if (!HALF_A) {
            #pragma unroll
            for (int it = 0; it < 4; it++) {
                int i = tid + it * 256;
                int r = i >> 3, q = i & 7;
                __half2 h[2];
                h[0] = __floats2half2_rn(raf[it].x, raf[it].y);
                h[1] = __floats2half2_rn(raf[it].z, raf[it].w);
                *(uint2*)&Ah[buf][r][q * 4] = *(const uint2*)h;
            }
        }
    };
    auto asyncA = [&](int kt, int buf) {
        if (HALF_A) {
            const __half* A = (const __half*)Av;
            int k0 = kt * BK;
            #pragma unroll
            for (int it = 0; it < 2; it++) {
                int i = tid + it * 256;
                int r = i >> 2, q = i & 3;
                if (rowBase + r < M)
                    CP_ASYNC16(smem_u32(&Ah[buf][r][q * 8]),
                               A + (size_t)(rowBase + r) * K + k0 + q * 8);
            }
        }
    };
    auto asyncB = [&](int kt, int buf) {
        int k0 = kt * BK;
        #pragma unroll
        for (int it = 0; it < BN / 64; it++) {
            int i = tid + it * 256;
            int r = i / (BN / 8), q = i % (BN / 8);
            CP_ASYNC16(smem_u32(&Bs[buf][r][q * 8]),
                       B + (size_t)(k0 + r) * Ncol + colBase + q * 8);
        }
    };
    auto compute = [&](int buf) {
        #pragma unroll
        for (int ks = 0; ks < BK; ks += 16) {
            uint32_t a[2][4];
            #pragma unroll
            for (int mt = 0; mt < 2; mt++) {
                int lrow = warpM * 32 + mt * 16 + (lane & 15);
                int lcol = ks + ((lane >> 4) << 3);
                uint32_t addr = smem_u32(&Ah[buf][lrow][lcol]);
                asm volatile(
                    "ldmatrix.sync.aligned.m8n8.x4.shared.b16 {%0,%1,%2,%3}, [%4];"
                    : "=r"(a[mt][0]), "=r"(a[mt][1]), "=r"(a[mt][2]), "=r"(a[mt][3])
                    : "r"(addr));
            }
            uint32_t b[NT][2];
            #pragma unroll
            for (int hb = 0; hb < NB; hb++) {
                int krow = ks + (lane & 15);
                int ncol = warpN * (BN / 2) + hb * 16 + ((lane >> 4) << 3);
                uint32_t addr = smem_u32(&Bs[buf][krow][ncol]);
                uint32_t r0, r1, r2, r3;
                asm volatile(
                    "ldmatrix.sync.aligned.m8n8.x4.trans.shared.b16 {%0,%1,%2,%3}, [%4];"
                    : "=r"(r0), "=r"(r1), "=r"(r2), "=r"(r3)
                    : "r"(addr));
                b[hb * 2 + 0][0] = r0; b[hb * 2 + 0][1] = r1;
                b[hb * 2 + 1][0] = r2; b[hb * 2 + 1][1] = r3;
            }
            #pragma unroll
            for (int mt = 0; mt < 2; mt++)
                #pragma unroll
                for (int nt = 0; nt < NT; nt++) {
                    asm volatile(
                        "mma.sync.aligned.m16n8k16.row.col.f32.f16.f16.f32 "
                        "{%0,%1,%2,%3}, {%4,%5,%6,%7}, {%8,%9}, {%0,%1,%2,%3};"
                        : "+f"(c[mt][nt][0]), "+f"(c[mt][nt][1]),
                          "+f"(c[mt][nt][2]), "+f"(c[mt][nt][3])
                        : "r"(a[mt][0]), "r"(a[mt][1]), "r"(a[mt][2]), "r"(a[mt][3]),
                          "r"(b[nt][0]), "r"(b[nt][1]));
                }
        }
    };

    asyncB(0, 0); asyncA(0, 0); CP_COMMIT();
    ldgA(0); stsA(0);
    CP_WAIT0();
    __syncthreads();
    for (int kt = 0; kt < nk; kt++) {
        int buf = kt & 1;
        if (kt + 1 < nk) {
            asyncB(kt + 1, buf ^ 1);
            asyncA(kt + 1, buf ^ 1);
            CP_COMMIT();
            ldgA(kt + 1);
        }
        compute(buf);
        if (kt + 1 < nk) {
            stsA(buf ^ 1);
            CP_WAIT0();
            __syncthreads();
        }
    }

    #pragma unroll
    for (int mt = 0; mt < 2; mt++) {
        int row0 = rowBase + warpM * 32 + mt * 16 + gid;
        #pragma unroll
        for (int nt = 0; nt < NT; nt++) {
            int col = colBase + warpN * (BN / 2) + nt * 8 + tig * 2;
            if (row0 < M)
                *(__half2*)(C + (size_t)row0 * Ncol + col) =
                    __floats2half2_rn(c[mt][nt][0], c[mt][nt][1]);
            if (row0 + 8 < M)
                *(__half2*)(C + (size_t)(row0 + 8) * Ncol + col) =
                    __floats2half2_rn(c[mt][nt][2], c[mt][nt][3]);
        }
    }

    if (ATT1) {
        // Each warp's 64-col slice == one head (BN=128, Ncol=256, grid.x=2).
        int head = blockIdx.x * 2 + warpN;
        const float* As_ = att_src + head * 64;
        const float* Ad_ = att_dst + head * 64;
        #pragma unroll
        for (int mt = 0; mt < 2; mt++) {
            float ps0 = 0.f, pd0 = 0.f, ps1 = 0.f, pd1 = 0.f;
            #pragma unroll
            for (int nt = 0; nt < NT; nt++) {
                int lc = nt * 8 + tig * 2;
                float w0 = As_[lc], w1 = As_[lc + 1];
                float v0 = Ad_[lc], v1 = Ad_[lc + 1];
                ps0 += c[mt][nt][0] * w0 + c[mt][nt][1] * w1;
                pd0 += c[mt][nt][0] * v0 + c[mt][nt][1] * v1;
                ps1 += c[mt][nt][2] * w0 + c[mt][nt][3] * w1;
                pd1 += c[mt][nt][2] * v0 + c[mt][nt][3] * v1;
            }
            #pragma unroll
            for (int o = 1; o < 4; o <<= 1) {
                ps0 += __shfl_xor_sync(0xffffffffu, ps0, o);
                pd0 += __shfl_xor_sync(0xffffffffu, pd0, o);
                ps1 += __shfl_xor_sync(0xffffffffu, ps1, o);
                pd1 += __shfl_xor_sync(0xffffffffu, pd1, o);
            }
            if (tig == 0) {
                int r0 = rowBase + warpM * 32 + mt * 16 + gid;
                if (r0 < M) {
                    g_asrc1[r0 * 4 + head] = ps0;
                    g_adst1[r0 * 4 + head] = pd0;
                }
                if (r0 + 8 < M) {
                    g_asrc1[(r0 + 8) * 4 + head] = ps1;
                    g_adst1[(r0 + 8) * 4 + head] = pd1;
                }
            }
        }
    }
}

// ---------------- CSR build ----------------
__global__ void init_cnt() {
    int i = blockIdx.x * blockDim.x + threadIdx.x;
    if (i < NN) g_cnt[i] = 1;  // self loop
}
__global__ void count_edges(const int* __restrict__ dst) {
    int e = blockIdx.x * blockDim.x + threadIdx.x;
    if (e < EE) atomicAdd(&g_cnt[dst[e]], 1);
}
__global__ void scan1() {
    __shared__ int wsum[32];
    int i = blockIdx.x * SCAN_BLK + threadIdx.x;
    int v = (i < NN) ? g_cnt[i] : 0;
    int lane = threadIdx.x & 31, wid = threadIdx.x >> 5;
    int incl = v;
    #pragma unroll
    for (int o = 1; o < 32; o <<= 1) {
        int t = __shfl_up_sync(0xffffffffu, incl, o);
        if (lane >= o) incl += t;
    }
    if (lane == 31) wsum[wid] = incl;
    __syncthreads();
    if (wid == 0) {
        int s = wsum[lane];
        #pragma unroll
        for (int o = 1; o < 32; o <<= 1) {
            int t = __shfl_up_sync(0xffffffffu, s, o);
            if (lane >= o) s += t;
        }
        wsum[lane] = s;
    }
    __syncthreads();
    int base = (wid > 0) ? wsum[wid - 1] : 0;
    incl += base;
    if (i < NN) g_rowptr[i] = incl - v;
    if (threadIdx.x == SCAN_BLK - 1) g_part[blockIdx.x] = incl;
}
__global__ void scan2() {
    if (threadIdx.x == 0) {
        int run = 0;
        for (int b = 0; b < NBLK_SCAN; b++) {
            int t = g_part[b];
            g_part[b] = run;
            run += t;
        }
        g_rowptr[NN] = run;
    }
}
__global__ void scan3() {
    int i = blockIdx.x * blockDim.x + threadIdx.x;
    if (i < NN) {
        int r = g_rowptr[i] + g_part[i >> 10];
        g_rowptr[i] = r;
        g_wpos[i] = r;
    }
}
__global__ void scatter_edges(const int* __restrict__ src, const int* __restrict__ dst) {
    int e = blockIdx.x * blockDim.x + threadIdx.x;
    if (e < EE) {
        int d = dst[e];
        int pos = atomicAdd(&g_wpos[d], 1);
        g_csr[pos] = src[e];
    } else if (e < EE + NN) {
        int i = e - EE;
        int pos = atomicAdd(&g_wpos[i], 1);
        g_csr[pos] = i;
    }
}

// ---------------- layer-1 aggregation: warp per dst node ----------------
__global__ __launch_bounds__(256) void aggregate1(const float* __restrict__ b1) {
    int node = blockIdx.x * 8 + (threadIdx.x >> 5);
    if (node >= NN) return;
    int lane = threadIdx.x & 31;
    int beg = g_rowptr[node], end = g_rowptr[node + 1];
    float4 ad = *(const float4*)(g_adst1 + node * 4);

    float m0 = -1e30f, m1 = -1e30f, m2 = -1e30f, m3 = -1e30f;
    for (int e = beg + lane; e < end; e += 32) {
        int s = g_csr[e];
        float4 as = *(const float4*)(g_asrc1 + s * 4);
        m0 = fmaxf(m0, lrelu(as.x + ad.x));
        m1 = fmaxf(m1, lrelu(as.y + ad.y));
        m2 = fmaxf(m2, lrelu(as.z + ad.z));
        m3 = fmaxf(m3, lrelu(as.w + ad.w));
    }
    m0 = warpMax(m0); m1 = warpMax(m1); m2 = warpMax(m2); m3 = warpMax(m3);

    float s0 = 0.f, s1 = 0.f, s2 = 0.f, s3 = 0.f;
    for (int e = beg + lane; e < end; e += 32) {
        int s = g_csr[e];
        float4 as = *(const float4*)(g_asrc1 + s * 4);
        s0 += expf(lrelu(as.x + ad.x) - m0);
        s1 += expf(lrelu(as.y + ad.y) - m1);
        s2 += expf(lrelu(as.z + ad.z) - m2);
        s3 += expf(lrelu(as.w + ad.w) - m3);
    }
    s0 = warpSum(s0); s1 = warpSum(s1); s2 = warpSum(s2); s3 = warpSum(s3);
    float i0 = 1.f / (s0 + 1e-16f), i1 = 1.f / (s1 + 1e-16f);
    float i2 = 1.f / (s2 + 1e-16f), i3 = 1.f / (s3 + 1e-16f);

    int head = lane >> 3;
    float mh  = head < 2 ? (head == 0 ? m0 : m1) : (head == 2 ? m2 : m3);
    float ih  = head < 2 ? (head == 0 ? i0 : i1) : (head == 2 ? i2 : i3);
    float adh = head < 2 ? (head == 0 ? ad.x : ad.y) : (head == 2 ? ad.z : ad.w);

    float acc[8];
    #pragma unroll
    for (int k = 0; k < 8; k++) acc[k] = 0.f;

    for (int e = beg; e < end; ++e) {
        int s = g_csr[e];
        float w = expf(lrelu(g_asrc1[s * 4 + head] + adh) - mh) * ih;
        uint4 raw = *(const uint4*)(g_h1h + (size_t)s * 256 + lane * 8);
        const __half2* hp = (const __half2*)&raw;
        #pragma unroll
        for (int q = 0; q < 4; q++) {
            float2 f = __half22float2(hp[q]);
            acc[q * 2]     = fmaf(w, f.x, acc[q * 2]);
            acc[q * 2 + 1] = fmaf(w, f.y, acc[q * 2 + 1]);
        }
    }
    const float* bb = b1 + lane * 8;
    __half2 o[4];
    #pragma unroll
    for (int q = 0; q < 4; q++) {
        float r0 = acc[q * 2]     + bb[q * 2];
        float r1 = acc[q * 2 + 1] + bb[q * 2 + 1];
        r0 = r0 > 0.f ? r0 : (expf(r0) - 1.f);
        r1 = r1 > 0.f ? r1 : (expf(r1) - 1.f);
        o[q] = __floats2half2_rn(r0, r1);
    }
    *(uint4*)(g_e1h + (size_t)node * 256 + lane * 8) = *(const uint4*)o;
}

// ---------------- attention coefficients, layer 2 (H=1, C=64) ----------------
__global__ void attn2(const float* __restrict__ att_src, const float* __restrict__ att_dst) {
    int node = blockIdx.x * 8 + (threadIdx.x >> 5);
    if (node >= NN) return;
    int lane = threadIdx.x & 31;
    float2 v = __half22float2(*(const __half2*)(g_h2h + (size_t)node * 64 + lane * 2));
    float ps = v.x * att_src[lane * 2] + v.y * att_src[lane * 2 + 1];
    float pd = v.x * att_dst[lane * 2] + v.y * att_dst[lane * 2 + 1];
    ps = warpSum(ps);
    pd = warpSum(pd);
    if (lane == 0) {
        g_asrc2[node] = ps;
        g_adst2[node] = pd;
    }
}

// ---------------- layer-2 aggregation ----------------
__global__ __launch_bounds__(256) void aggregate2(const float* __restrict__ b2) {
    int node = blockIdx.x * 8 + (threadIdx.x >> 5);
    if (node >= NN) return;
    int lane = threadIdx.x & 31;
    int beg = g_rowptr[node], end = g_rowptr[node + 1];
    float adv = g_adst2[node];

    float m = -1e30f;
    for (int e = beg + lane; e < end; e += 32)
        m = fmaxf(m, lrelu(g_asrc2[g_csr[e]] + adv));
    m = warpMax(m);
    float sm = 0.f;
    for (int e = beg + lane; e < end; e += 32)
        sm += expf(lrelu(g_asrc2[g_csr[e]] + adv) - m);
    sm = warpSum(sm);
    float inv = 1.f / (sm + 1e-16f);

    float a0 = 0.f, a1 = 0.f;
    for (int e = beg; e < end; ++e) {
        int s = g_csr[e];
        float w = expf(lrelu(g_asrc2[s] + adv) - m) * inv;
        float2 v = __half22float2(*(const __half2*)(g_h2h + (size_t)s * 64 + lane * 2));
        a0 = fmaf(w, v.x, a0);
        a1 = fmaf(w, v.y, a1);
    }
    g_o2[(size_t)node * 64 + lane * 2]     = a0 + b2[lane * 2];
    g_o2[(size_t)node * 64 + lane * 2 + 1] = a1 + b2[lane * 2 + 1];
}

// ---------------- global mean pool (batch is sorted) ----------------
__device__ __forceinline__ int lower_bound_i(const int* b, int n, int v) {
    int lo = 0, hi = n;
    while (lo < hi) {
        int mid = (lo + hi) >> 1;
        if (b[mid] < v) lo = mid + 1; else hi = mid;
    }
    return lo;
}
__global__ void pool(const int* __restrict__ batch) {
    __shared__ float part[256];
    __shared__ int sb, se;
    int g = blockIdx.x;
    if (threadIdx.x == 0) {
        sb = lower_bound_i(batch, NN, g);
        se = lower_bound_i(batch, NN, g + 1);
    }
    __syncthreads();
    int c = threadIdx.x & 63, q = threadIdx.x >> 6;
    float s = 0.f;
    for (int i = sb + q; i < se; i += 4) s += g_o2[(size_t)i * 64 + c];
    part[threadIdx.x] = s;
    __syncthreads();
    if (q == 0) {
        float t = part[c] + part[c + 64] + part[c + 128] + part[c + 192];
        float cnt = (float)(se - sb);
        g_emb[g * 64 + c] = t / fmaxf(cnt, 1.f);
    }
}

// ---------------- final MLP ----------------
__global__ void mlp(const float* __restrict__ W3, const float* __restrict__ b3,
                    const float* __restrict__ W4, const float* __restrict__ b4,
                    float* __restrict__ out) {
    __shared__ float w3[64 * 32], w4[64], bb3[32], bb4[2];
    int t = threadIdx.x;
    for (int i = t; i < 2048; i += 64) w3[i] = W3[i];
    w4[t] = W4[t];
    if (t < 32) bb3[t] = b3[t];
    if (t < 2) bb4[t] = b4[t];
    __syncthreads();
    float e[64];
    #pragma unroll
    for (int k = 0; k < 64; k++) e[k] = g_emb[t * 64 + k];
    float l0 = bb4[0], l1 = bb4[1];
    #pragma unroll 4
    for (int j = 0; j < 32; j++) {
        float z = bb3[j];
        #pragma unroll
        for (int k = 0; k < 64; k++) z = fmaf(e[k], w3[k * 32 + j], z);
        z = fmaxf(z, 0.f);
        l0 = fmaf(z, w4[j * 2], l0);
        l1 = fmaf(z, w4[j * 2 + 1], l1);
    }
    out[t * 2] = l0;
    out[t * 2 + 1] = l1;
}

// ---------------- launch ----------------
extern "C" void kernel_launch(void* const* d_in, const int* in_sizes, int n_in,
                              void* d_out, int out_size) {
    const float* x = (const float*)d_in[0];
    const int* ei = (const int*)d_in[1];
    const int* batch = (const int*)d_in[2];
    const float* W1 = (const float*)d_in[3];
    const float* as1 = (const float*)d_in[4];
    const float* ad1 = (const float*)d_in[5];
    const float* b1 = (const float*)d_in[6];
    const float* W2 = (const float*)d_in[7];
    const float* as2 = (const float*)d_in[8];
    const float* ad2 = (const float*)d_in[9];
    const float* b2 = (const float*)d_in[10];
    const float* W3 = (const float*)d_in[11];
    const float* b3 = (const float*)d_in[12];
    const float* W4 = (const float*)d_in[13];
    const float* b4 = (const float*)d_in[14];
    float* out = (float*)d_out;

    const int* e_src = ei;
    const int* e_dst = ei + EE;

    void* p;
    cudaGetSymbolAddress(&p, g_h1h);  __half* h1 = (__half*)p;
    cudaGetSymbolAddress(&p, g_e1h);  __half* e1 = (__half*)p;
    cudaGetSymbolAddress(&p, g_h2h);  __half* h2 = (__half*)p;
    cudaGetSymbolAddress(&p, g_w1h);  __half* w1h = (__half*)p;
    cudaGetSymbolAddress(&p, g_w2h);  __half* w2h = (__half*)p;

    // side stream + events, created once on first (non-captured) call
    static cudaStream_t sB = nullptr;
    static cudaEvent_t evRoot = nullptr, evB = nullptr;
    if (!sB) {
        cudaStreamCreateWithFlags(&sB, cudaStreamNonBlocking);
        cudaEventCreateWithFlags(&evRoot, cudaEventDisableTiming);
        cudaEventCreateWithFlags(&evB, cudaEventDisableTiming);
    }

    const int agg_blocks = NN / 8;  // 12500, exact

    // ---- fork: CSR build on side stream, GEMM1(+att1) on main ----
    cudaEventRecord(evRoot, 0);
    cudaStreamWaitEvent(sB, evRoot, 0);

    prepW<<<256, 256>>>(W1, W2);                                   // main
    init_cnt<<<(NN + 255) / 256, 256, 0, sB>>>();                  // side
    count_edges<<<(EE + 255) / 256, 256, 0, sB>>>(e_dst);
    // GEMM1: h1 = x @ W1 [100000,256], attention dots fused in epilogue
    gemm_h<128, false, true><<<dim3(2, 782), 256>>>(x, w1h, h1, NN, 256, 256, as1, ad1);
    scan1<<<NBLK_SCAN, SCAN_BLK, 0, sB>>>();
    scan2<<<1, 32, 0, sB>>>();
    scan3<<<(NN + 255) / 256, 256, 0, sB>>>();
    scatter_edges<<<(EE + NN + 255) / 256, 256, 0, sB>>>(e_src, e_dst);
    cudaEventRecord(evB, sB);

    // ---- join ----
    cudaStreamWaitEvent(0, evB, 0);

    // layer-1 softmax-aggregate + ELU
    aggregate1<<<agg_blocks, 256>>>(b1);
    // GEMM2: h2 = e1 @ W2 [100000,64]
    gemm_h<64, true, false><<<dim3(1, 782), 256>>>(e1, w2h, h2, NN, 256, 64, nullptr, nullptr);
    attn2<<<agg_blocks, 256>>>(as2, ad2);
    aggregate2<<<agg_blocks, 256>>>(b2);
    pool<<<GG, 256>>>(batch);
    mlp<<<1, 64>>>(W3, b3, W4, b4, out);
}